// round 8
// baseline (speedup 1.0000x reference)
#include <cuda_runtime.h>
#include <cstdint>

// MLPDecoder, split + tf32 mma.sync, persistent + de-chunked (2 syncs/tile).
// logit[e] = relu([zu,zv,|zu-zv|]@W1 + b1)@W2 + b2
//  prep: g_Wab[j][k]=tf32(W1ab^T), g_Wc[j][k]=tf32(W1c^T)
//  k1:   AB[n][0:256] = [ z[n]@W1a , z[n]@W1b ]   (persistent, W resident)
//  k2:   C = |zu-zv| @ W1c (K=128, W resident); h = relu(C + ABu + ABv + b1);
//        out = h@W2 + b2  (fused epilogue)
// edge_index is int32 on the wire (JAX x64 disabled).

#define DIM 128
#define NMAX 100000

__device__ float g_Wab[256 * 128];   // [j][k] tf32
__device__ float g_Wc[128 * 128];    // [j][k] tf32
__device__ float g_AB[(size_t)NMAX * 256];

__device__ __forceinline__ uint32_t f2tf(float x) {
    uint32_t r; asm("cvt.rna.tf32.f32 %0, %1;" : "=r"(r) : "f"(x)); return r;
}
__device__ __forceinline__ float tfpack(float x) { return __uint_as_float(f2tf(x)); }
__device__ __forceinline__ float4 tf4(float4 a) {
    float4 o; o.x = tfpack(a.x); o.y = tfpack(a.y); o.z = tfpack(a.z); o.w = tfpack(a.w);
    return o;
}
__device__ __forceinline__ void ldsm4(uint32_t& r0, uint32_t& r1, uint32_t& r2, uint32_t& r3,
                                      uint32_t addr) {
    asm volatile("ldmatrix.sync.aligned.m8n8.x4.shared.b16 {%0,%1,%2,%3}, [%4];"
                 : "=r"(r0), "=r"(r1), "=r"(r2), "=r"(r3) : "r"(addr));
}
__device__ __forceinline__ void mma_tf32(
    float& c0, float& c1, float& c2, float& c3,
    uint32_t a0, uint32_t a1, uint32_t a2, uint32_t a3,
    uint32_t b0, uint32_t b1)
{
    asm volatile(
        "mma.sync.aligned.m16n8k8.row.col.f32.tf32.tf32.f32 "
        "{%0,%1,%2,%3}, {%4,%5,%6,%7}, {%8,%9}, {%0,%1,%2,%3};"
        : "+f"(c0), "+f"(c1), "+f"(c2), "+f"(c3)
        : "r"(a0), "r"(a1), "r"(a2), "r"(a3), "r"(b0), "r"(b1));
}

// ---------------------------------------------------------------------------
__global__ void prep_w(const float* __restrict__ W1) {
    int i = blockIdx.x * 256 + threadIdx.x;
    if (i < 32768) {                       // Wab
        int j = i >> 7, k = i & 127;
        g_Wab[i] = tfpack(W1[(k + (j < 128 ? 0 : 128)) * 128 + (j & 127)]);
    } else if (i < 49152) {                // Wc
        int l = i - 32768;
        int j = l >> 7, k = l & 127;
        g_Wc[l] = tfpack(W1[(256 + k) * 128 + j]);
    }
}

// ---------------------------------------------------------------------------
// Kernel 1 (persistent): AB = z @ [W1a|W1b].  Tile 128 rows x 256 cols, K=128.
// 512 threads, warp tile 32r x 64c. smem: sW 131072 + sZ 65536 = 196608.
// ---------------------------------------------------------------------------
__global__ __launch_bounds__(512, 1) void ab_gemm(
    const float* __restrict__ z, float* __restrict__ AB, int N, int ntiles)
{
    extern __shared__ __align__(16) unsigned char smem[];
    const int tid  = threadIdx.x;
    const int warp = tid >> 5;
    const int lane = tid & 31;
    const int wy = warp >> 2, wx = warp & 3;
    const int gid = lane >> 2, tig = lane & 3;

    // stage W once: 8192 float4, rows j (512B) XOR-swizzled
    #pragma unroll
    for (int p = 0; p < 16; p++) {
        int i = p * 512 + tid;
        int j = i >> 5, uu = i & 31;
        float4 w = __ldg((const float4*)g_Wab + (size_t)j * 32 + uu);
        *(float4*)(smem + j * 512 + ((uu ^ (j & 7)) << 4)) = w;
    }

    const uint32_t sWb = (uint32_t)__cvta_generic_to_shared(smem);
    const uint32_t sZb = sWb + 131072;
    const int l7 = lane & 7;
    const int roffA = ((lane >> 3) & 1) * 8, cselA = (lane >> 4) & 1;
    const int roffB = ((lane >> 4) & 1) * 8, cselB = (lane >> 3) & 1;

    const int r_s = tid & 127;         // row in tile
    const int h_s = tid >> 7;          // 0..3, k quarter
    const int e7x = r_s & 7;
    __syncthreads();

    for (int tile = blockIdx.x; tile < ntiles; tile += gridDim.x) {
        const int rowBase = tile * 128;
        // stage z full-K for this tile (tf32, swizzled)
        {
            int zr = rowBase + r_s; if (zr >= N) zr = N - 1;
            const float4* src = (const float4*)(z + (size_t)zr * DIM + h_s * 32);
            unsigned char* dst = smem + 131072 + r_s * 512;
            #pragma unroll
            for (int q = 0; q < 8; q++) {
                float4 a = __ldg(src + q);
                int uu = h_s * 8 + q;
                *(float4*)(dst + ((uu ^ e7x) << 4)) = tf4(a);
            }
        }
        __syncthreads();

        float c[2][8][4];
        #pragma unroll
        for (int m = 0; m < 2; m++)
            #pragma unroll
            for (int n = 0; n < 8; n++)
                #pragma unroll
                for (int q = 0; q < 4; q++) c[m][n][q] = 0.f;

        #pragma unroll
        for (int ks = 0; ks < 16; ks++) {
            const uint32_t swzA = (uint32_t)(((2 * ks + cselA) ^ l7)) << 4;
            const uint32_t swzB = (uint32_t)(((2 * ks + cselB) ^ l7)) << 4;
            uint32_t a[2][4];
            #pragma unroll
            for (int mt = 0; mt < 2; mt++)
                ldsm4(a[mt][0], a[mt][1], a[mt][2], a[mt][3],
                      sZb + (uint32_t)(32 * wy + 16 * mt + roffA + l7) * 512 + swzA);
            #pragma unroll
            for (int g = 0; g < 4; g++) {
                uint32_t b[4];
                ldsm4(b[0], b[1], b[2], b[3],
                      sWb + (uint32_t)(64 * wx + 16 * g + roffB + l7) * 512 + swzB);
                #pragma unroll
                for (int mt = 0; mt < 2; mt++) {
                    mma_tf32(c[mt][2*g  ][0], c[mt][2*g  ][1], c[mt][2*g  ][2], c[mt][2*g  ][3],
                             a[mt][0], a[mt][1], a[mt][2], a[mt][3], b[0], b[1]);
                    mma_tf32(c[mt][2*g+1][0], c[mt][2*g+1][1], c[mt][2*g+1][2], c[mt][2*g+1][3],
                             a[mt][0], a[mt][1], a[mt][2], a[mt][3], b[2], b[3]);
                }
            }
        }

        #pragma unroll
        for (int mt = 0; mt < 2; mt++) {
            int r0 = rowBase + 32 * wy + 16 * mt + gid;
            int r1 = r0 + 8;
            #pragma unroll
            for (int nt = 0; nt < 8; nt++) {
                int col = 64 * wx + 8 * nt + 2 * tig;
                if (r0 < N) *(float2*)(AB + (size_t)r0 * 256 + col) = make_float2(c[mt][nt][0], c[mt][nt][1]);
                if (r1 < N) *(float2*)(AB + (size_t)r1 * 256 + col) = make_float2(c[mt][nt][2], c[mt][nt][3]);
            }
        }
        __syncthreads();   // sZ readers done before next tile restages
    }
}

// ---------------------------------------------------------------------------
// Kernel 2 (persistent): per 128-edge tile, C = diff @ W1c (K=128), fused head.
// 512 threads, warp tile 32e x 32j.
// smem: sW 65536 + sF 65536 + sS[128][132] 67584 + b1 512 + w2 512 + sP 2048.
// ---------------------------------------------------------------------------
#define K2_SF   65536
#define K2_SS   131072
#define K2_SB1  198656
#define K2_SW2  199168
#define K2_SP   199680
#define K2_SMEM 201728

__global__ __launch_bounds__(512, 1) void edge_mlp(
    const float* __restrict__ z, const int* __restrict__ eidx,
    const float* __restrict__ b1, const float* __restrict__ W2,
    const float* __restrict__ b2, const float* __restrict__ AB,
    float* __restrict__ out, int E, int ntiles)
{
    extern __shared__ __align__(16) unsigned char smem[];
    float* sS  = (float*)(smem + K2_SS);      // [128e][132]
    float* sb1 = (float*)(smem + K2_SB1);
    float* sw2 = (float*)(smem + K2_SW2);
    float* sP  = (float*)(smem + K2_SP);      // [128e][4]

    const int tid  = threadIdx.x;
    const int warp = tid >> 5;
    const int lane = tid & 31;
    const int wy = warp >> 2, wx = warp & 3;
    const int gid = lane >> 2, tig = lane & 3;

    if (tid < 128) { sb1[tid] = b1[tid]; sw2[tid] = W2[tid]; }

    // stage W1c once: 4096 float4
    #pragma unroll
    for (int p = 0; p < 8; p++) {
        int i = p * 512 + tid;
        int j = i >> 5, uu = i & 31;
        float4 w = __ldg((const float4*)g_Wc + (size_t)j * 32 + uu);
        *(float4*)(smem + j * 512 + ((uu ^ (j & 7)) << 4)) = w;
    }

    const uint32_t sWb = (uint32_t)__cvta_generic_to_shared(smem);
    const uint32_t sFb = sWb + K2_SF;
    const int l7 = lane & 7;
    const int roffA = ((lane >> 3) & 1) * 8, cselA = (lane >> 4) & 1;
    const int roffB = ((lane >> 4) & 1) * 8, cselB = (lane >> 3) & 1;

    const int e_s = tid & 127;          // edge within tile
    const int h_s = tid >> 7;           // 0..3, k/j quarter
    const int e7x = e_s & 7;
    const float bias2 = __ldg(b2);
    __syncthreads();

    // preload b1/w2 pairs for this thread's j's
    float b1r[4][2], w2r[4][2];
    #pragma unroll
    for (int nt = 0; nt < 4; nt++) {
        int j = 32 * wx + 8 * nt + 2 * tig;
        b1r[nt][0] = sb1[j]; b1r[nt][1] = sb1[j + 1];
        w2r[nt][0] = sw2[j]; w2r[nt][1] = sw2[j + 1];
    }

    for (int tile = blockIdx.x; tile < ntiles; tile += gridDim.x) {
        const int eBase = tile * 128;
        // ---- stage: diffs (tf32, swizzled) + S = ABu+ABv (fp32) ----
        {
            const int ge = eBase + e_s;
            int u = 0, v = 0;
            if (ge < E) { u = eidx[ge]; v = eidx[E + ge]; }
            const float4* pu = (const float4*)(z + (size_t)u * DIM + h_s * 32);
            const float4* pv = (const float4*)(z + (size_t)v * DIM + h_s * 32);
            const float4* au = (const float4*)(AB + (size_t)u * 256 + 32 * h_s);
            const float4* av = (const float4*)(AB + (size_t)v * 256 + 128 + 32 * h_s);
            unsigned char* fdst = smem + K2_SF + e_s * 512;
            float* sdst = sS + e_s * 132 + 32 * h_s;
            #pragma unroll
            for (int q = 0; q < 8; q++) {
                float4 a = __ldg(pu + q), b = __ldg(pv + q);
                float4 d;
                d.x = fabsf(a.x - b.x); d.y = fabsf(a.y - b.y);
                d.z = fabsf(a.z - b.z); d.w = fabsf(a.w - b.w);
                int uu = h_s * 8 + q;
                *(float4*)(fdst + ((uu ^ e7x) << 4)) = tf4(d);
                float4 p = __ldg(au + q), qq = __ldg(av + q);
                float4 s;
                s.x = p.x + qq.x; s.y = p.y + qq.y; s.z = p.z + qq.z; s.w = p.w + qq.w;
                *(float4*)(sdst + q * 4) = s;
            }
        }
        __syncthreads();

        // ---- MMA: 16 k-steps, uninterrupted ----
        float c[2][4][4];
        #pragma unroll
        for (int m = 0; m < 2; m++)
            #pragma unroll
            for (int n = 0; n < 4; n++)
                #pragma unroll
                for (int q = 0; q < 4; q++) c[m][n][q] = 0.f;

        #pragma unroll
        for (int ks = 0; ks < 16; ks++) {
            const uint32_t swzA = (uint32_t)(((2 * ks + cselA) ^ l7)) << 4;
            const uint32_t swzB = (uint32_t)(((2 * ks + cselB) ^ l7)) << 4;
            uint32_t a[2][4];
            #pragma unroll
            for (int mt = 0; mt < 2; mt++)
                ldsm4(a[mt][0], a[mt][1], a[mt][2], a[mt][3],
                      sFb + (uint32_t)(32 * wy + 16 * mt + roffA + l7) * 512 + swzA);
            #pragma unroll
            for (int g = 0; g < 2; g++) {
                uint32_t b[4];
                ldsm4(b[0], b[1], b[2], b[3],
                      sWb + (uint32_t)(32 * wx + 16 * g + roffB + l7) * 512 + swzB);
                #pragma unroll
                for (int mt = 0; mt < 2; mt++) {
                    mma_tf32(c[mt][2*g  ][0], c[mt][2*g  ][1], c[mt][2*g  ][2], c[mt][2*g  ][3],
                             a[mt][0], a[mt][1], a[mt][2], a[mt][3], b[0], b[1]);
                    mma_tf32(c[mt][2*g+1][0], c[mt][2*g+1][1], c[mt][2*g+1][2], c[mt][2*g+1][3],
                             a[mt][0], a[mt][1], a[mt][2], a[mt][3], b[2], b[3]);
                }
            }
        }

        // ---- epilogue ----
        float pe[2][2] = {{0.f, 0.f}, {0.f, 0.f}};
        #pragma unroll
        for (int mt = 0; mt < 2; mt++) {
            int e0 = 32 * wy + 16 * mt + gid;
            #pragma unroll
            for (int nt = 0; nt < 4; nt++) {
                int j = 32 * wx + 8 * nt + 2 * tig;
                const float* s0 = sS + e0 * 132 + j;
                const float* s1 = sS + (e0 + 8) * 132 + j;
                pe[mt][0] += fmaxf(c[mt][nt][0] + s0[0] + b1r[nt][0], 0.f) * w2r[nt][0]
                           + fmaxf(c[mt][nt][1] + s0[1] + b1r[nt][1], 0.f) * w2r[nt][1];
                pe[mt][1] += fmaxf(c[mt][nt][2] + s1[0] + b1r[nt][0], 0.f) * w2r[nt][0]
                           + fmaxf(c[mt][nt][3] + s1[1] + b1r[nt][1], 0.f) * w2r[nt][1];
            }
        }
        #pragma unroll
        for (int mt = 0; mt < 2; mt++)
            #pragma unroll
            for (int hh = 0; hh < 2; hh++) {
                float p = pe[mt][hh];
                p += __shfl_xor_sync(0xFFFFFFFFu, p, 1);
                p += __shfl_xor_sync(0xFFFFFFFFu, p, 2);
                if (tig == 0) sP[(32 * wy + 16 * mt + 8 * hh + gid) * 4 + wx] = p;
            }
        __syncthreads();

        if (tid < 128) {
            int g = eBase + tid;
            if (g < E)
                out[g] = sP[tid * 4] + sP[tid * 4 + 1] + sP[tid * 4 + 2] + sP[tid * 4 + 3] + bias2;
        }
        // no extra sync: next stage writes sF/sS (readers passed sync above);
        // sP next written only after next tile's post-stage sync.
    }
}

extern "C" void kernel_launch(void* const* d_in, const int* in_sizes, int n_in,
                              void* d_out, int out_size) {
    const float* z    = (const float*)d_in[0];
    const int*   eidx = (const int*)d_in[1];   // int32 on the wire
    const float* W1   = (const float*)d_in[2];
    const float* b1   = (const float*)d_in[3];
    const float* W2   = (const float*)d_in[4];
    const float* b2   = (const float*)d_in[5];
    float*       out  = (float*)d_out;

    const int N = in_sizes[0] / DIM;           // 100000
    const int E = in_sizes[1] / 2;             // 500000
    const int t1 = (N + 127) / 128;            // 782
    const int t2 = (E + 127) / 128;            // 3907

    float* AB = nullptr;
    cudaGetSymbolAddress((void**)&AB, g_AB);

    const int k1_smem = 131072 + 65536;        // 196608
    cudaFuncSetAttribute(ab_gemm,  cudaFuncAttributeMaxDynamicSharedMemorySize, k1_smem);
    cudaFuncSetAttribute(edge_mlp, cudaFuncAttributeMaxDynamicSharedMemorySize, K2_SMEM);

    prep_w<<<192, 256>>>(W1);
    ab_gemm<<<148, 512, k1_smem>>>(z, AB, N, t1);
    edge_mlp<<<148, 512, K2_SMEM>>>(z, eidx, b1, W2, b2, AB, out, E, t2);
}

// round 9
// speedup vs baseline: 1.7625x; 1.7625x over previous
#include <cuda_runtime.h>
#include <cstdint>

// MLPDecoder, split + tf32 mma.sync; persistent W + 4-chunk double-buffered
// pipeline with register prefetch (LDG issued before MMA, STS after).
// logit[e] = relu([zu,zv,|zu-zv|]@W1 + b1)@W2 + b2
//  prep: g_Wab[j][k]=tf32(W1ab^T), g_Wc[j][k]=tf32(W1c^T)
//  k1:   AB[n][0:256] = [ z[n]@W1a , z[n]@W1b ]
//  k2:   C = |zu-zv| @ W1c; h = relu(C + ABu + ABv + b1); out = h@W2 + b2
// edge_index is int32 on the wire (JAX x64 disabled).

#define DIM 128
#define NMAX 100000

__device__ float g_Wab[256 * 128];   // [j][k] tf32
__device__ float g_Wc[128 * 128];    // [j][k] tf32
__device__ float g_AB[(size_t)NMAX * 256];

__device__ __forceinline__ uint32_t f2tf(float x) {
    uint32_t r; asm("cvt.rna.tf32.f32 %0, %1;" : "=r"(r) : "f"(x)); return r;
}
__device__ __forceinline__ float tfpack(float x) { return __uint_as_float(f2tf(x)); }
__device__ __forceinline__ float4 tf4(float4 a) {
    float4 o; o.x = tfpack(a.x); o.y = tfpack(a.y); o.z = tfpack(a.z); o.w = tfpack(a.w);
    return o;
}
__device__ __forceinline__ void ldsm4(uint32_t& r0, uint32_t& r1, uint32_t& r2, uint32_t& r3,
                                      uint32_t addr) {
    asm volatile("ldmatrix.sync.aligned.m8n8.x4.shared.b16 {%0,%1,%2,%3}, [%4];"
                 : "=r"(r0), "=r"(r1), "=r"(r2), "=r"(r3) : "r"(addr));
}
__device__ __forceinline__ void mma_tf32(
    float& c0, float& c1, float& c2, float& c3,
    uint32_t a0, uint32_t a1, uint32_t a2, uint32_t a3,
    uint32_t b0, uint32_t b1)
{
    asm volatile(
        "mma.sync.aligned.m16n8k8.row.col.f32.tf32.tf32.f32 "
        "{%0,%1,%2,%3}, {%4,%5,%6,%7}, {%8,%9}, {%0,%1,%2,%3};"
        : "+f"(c0), "+f"(c1), "+f"(c2), "+f"(c3)
        : "r"(a0), "r"(a1), "r"(a2), "r"(a3), "r"(b0), "r"(b1));
}

// ---------------------------------------------------------------------------
__global__ void prep_w(const float* __restrict__ W1) {
    int i = blockIdx.x * 256 + threadIdx.x;
    if (i < 32768) {                       // Wab
        int j = i >> 7, k = i & 127;
        g_Wab[i] = tfpack(W1[(k + (j < 128 ? 0 : 128)) * 128 + (j & 127)]);
    } else if (i < 49152) {                // Wc
        int l = i - 32768;
        int j = l >> 7, k = l & 127;
        g_Wc[l] = tfpack(W1[(256 + k) * 128 + j]);
    }
}

// ---------------------------------------------------------------------------
// Kernel 1 (persistent): AB = z @ [W1a|W1b]. Tile 128r x 256c, K=128 in 4 chunks.
// 512 threads, warp tile 32r x 64c. smem: sW 131072 + sZ 2x16384 = 163840.
// ---------------------------------------------------------------------------
__global__ __launch_bounds__(512, 1) void ab_gemm(
    const float* __restrict__ z, float* __restrict__ AB, int N, int ntiles)
{
    extern __shared__ __align__(16) unsigned char smem[];
    const int tid  = threadIdx.x;
    const int warp = tid >> 5;
    const int lane = tid & 31;
    const int wy = warp >> 2, wx = warp & 3;
    const int gid = lane >> 2, tig = lane & 3;

    // stage W once (rows 512B, XOR swizzled)
    #pragma unroll
    for (int p = 0; p < 16; p++) {
        int i = p * 512 + tid;
        int j = i >> 5, uu = i & 31;
        float4 w = __ldg((const float4*)g_Wab + (size_t)j * 32 + uu);
        *(float4*)(smem + j * 512 + ((uu ^ (j & 7)) << 4)) = w;
    }

    const uint32_t sWb = (uint32_t)__cvta_generic_to_shared(smem);
    const uint32_t sZb = sWb + 131072;
    const int l7 = lane & 7;
    const int roffA = ((lane >> 3) & 1) * 8, cselA = (lane >> 4) & 1;
    const int roffB = ((lane >> 4) & 1) * 8, cselB = (lane >> 3) & 1;

    const int r_s = tid & 127;
    const int q4  = tid >> 7;          // 0..3 -> 8 floats of the 32-float chunk
    const int e7x = r_s & 7;
    __syncthreads();

    for (int tile = blockIdx.x; tile < ntiles; tile += gridDim.x) {
        const int rowBase = tile * 128;
        int zr = rowBase + r_s; if (zr >= N) zr = N - 1;
        const float* zrow = z + (size_t)zr * DIM;

        auto ld2 = [&](int c, float4& A0, float4& A1) {
            const float4* src = (const float4*)(zrow + c * 32 + q4 * 8);
            A0 = __ldg(src); A1 = __ldg(src + 1);
        };
        auto st2 = [&](int c, float4 A0, float4 A1) {
            unsigned char* dst = smem + 131072 + (c & 1) * 16384 + r_s * 128;
            int uu = q4 * 2;
            *(float4*)(dst + ((uu ^ e7x) << 4))       = tf4(A0);
            *(float4*)(dst + (((uu + 1) ^ e7x) << 4)) = tf4(A1);
        };

        { float4 A0, A1; ld2(0, A0, A1); st2(0, A0, A1); }
        __syncthreads();

        float c[2][8][4];
        #pragma unroll
        for (int m = 0; m < 2; m++)
            #pragma unroll
            for (int n = 0; n < 8; n++)
                #pragma unroll
                for (int q = 0; q < 4; q++) c[m][n][q] = 0.f;

        #pragma unroll
        for (int ch = 0; ch < 4; ch++) {
            float4 P0, P1;
            if (ch < 3) ld2(ch + 1, P0, P1);          // prefetch before MMA

            const uint32_t zbuf = sZb + (ch & 1) * 16384;
            #pragma unroll
            for (int ks = 0; ks < 4; ks++) {
                const int kk = ch * 4 + ks;
                const uint32_t swzA = (uint32_t)(((2 * ks + cselA) ^ l7)) << 4;
                const uint32_t swzB = (uint32_t)(((2 * kk + cselB) ^ l7)) << 4;
                uint32_t a[2][4];
                #pragma unroll
                for (int mt = 0; mt < 2; mt++)
                    ldsm4(a[mt][0], a[mt][1], a[mt][2], a[mt][3],
                          zbuf + (uint32_t)(32 * wy + 16 * mt + roffA + l7) * 128 + swzA);
                #pragma unroll
                for (int g = 0; g < 4; g++) {
                    uint32_t b[4];
                    ldsm4(b[0], b[1], b[2], b[3],
                          sWb + (uint32_t)(64 * wx + 16 * g + roffB + l7) * 512 + swzB);
                    #pragma unroll
                    for (int mt = 0; mt < 2; mt++) {
                        mma_tf32(c[mt][2*g  ][0], c[mt][2*g  ][1], c[mt][2*g  ][2], c[mt][2*g  ][3],
                                 a[mt][0], a[mt][1], a[mt][2], a[mt][3], b[0], b[1]);
                        mma_tf32(c[mt][2*g+1][0], c[mt][2*g+1][1], c[mt][2*g+1][2], c[mt][2*g+1][3],
                                 a[mt][0], a[mt][1], a[mt][2], a[mt][3], b[2], b[3]);
                    }
                }
            }
            if (ch < 3) st2(ch + 1, P0, P1);          // store prefetch after MMA
            __syncthreads();
        }

        #pragma unroll
        for (int mt = 0; mt < 2; mt++) {
            int r0 = rowBase + 32 * wy + 16 * mt + gid;
            int r1 = r0 + 8;
            #pragma unroll
            for (int nt = 0; nt < 8; nt++) {
                int col = 64 * wx + 8 * nt + 2 * tig;
                if (r0 < N) *(float2*)(AB + (size_t)r0 * 256 + col) = make_float2(c[mt][nt][0], c[mt][nt][1]);
                if (r1 < N) *(float2*)(AB + (size_t)r1 * 256 + col) = make_float2(c[mt][nt][2], c[mt][nt][3]);
            }
        }
        __syncthreads();
    }
}

// ---------------------------------------------------------------------------
// Kernel 2 (persistent): C = |zu-zv| @ W1c (K=128, 4 chunks), fused MLP head.
// 512 threads, warp tile 32e x 32j.
// smem: sW 65536 + sF 2x16384 + sS[128][132] 67584 + b1/w2 1024 + sP 2048.
// ---------------------------------------------------------------------------
#define K2_SF   65536
#define K2_SS   98304
#define K2_SB1  165888
#define K2_SW2  166400
#define K2_SP   166912
#define K2_SMEM 168960

__global__ __launch_bounds__(512, 1) void edge_mlp(
    const float* __restrict__ z, const int* __restrict__ eidx,
    const float* __restrict__ b1, const float* __restrict__ W2,
    const float* __restrict__ b2, const float* __restrict__ AB,
    float* __restrict__ out, int E, int ntiles)
{
    extern __shared__ __align__(16) unsigned char smem[];
    float* sS  = (float*)(smem + K2_SS);
    float* sb1 = (float*)(smem + K2_SB1);
    float* sw2 = (float*)(smem + K2_SW2);
    float* sP  = (float*)(smem + K2_SP);

    const int tid  = threadIdx.x;
    const int warp = tid >> 5;
    const int lane = tid & 31;
    const int wy = warp >> 2, wx = warp & 3;
    const int gid = lane >> 2, tig = lane & 3;

    if (tid < 128) { sb1[tid] = b1[tid]; sw2[tid] = W2[tid]; }

    #pragma unroll
    for (int p = 0; p < 8; p++) {
        int i = p * 512 + tid;
        int j = i >> 5, uu = i & 31;
        float4 w = __ldg((const float4*)g_Wc + (size_t)j * 32 + uu);
        *(float4*)(smem + j * 512 + ((uu ^ (j & 7)) << 4)) = w;
    }

    const uint32_t sWb = (uint32_t)__cvta_generic_to_shared(smem);
    const uint32_t sFb = sWb + K2_SF;
    const int l7 = lane & 7;
    const int roffA = ((lane >> 3) & 1) * 8, cselA = (lane >> 4) & 1;
    const int roffB = ((lane >> 4) & 1) * 8, cselB = (lane >> 3) & 1;

    const int e_s = tid & 127;
    const int q4  = tid >> 7;           // 0..3 -> 8 floats of each 32-float chunk
    const int e7x = e_s & 7;
    const float bias2 = __ldg(b2);
    __syncthreads();

    float b1r[4][2], w2r[4][2];
    #pragma unroll
    for (int nt = 0; nt < 4; nt++) {
        int j = 32 * wx + 8 * nt + 2 * tig;
        b1r[nt][0] = sb1[j]; b1r[nt][1] = sb1[j + 1];
        w2r[nt][0] = sw2[j]; w2r[nt][1] = sw2[j + 1];
    }

    for (int tile = blockIdx.x; tile < ntiles; tile += gridDim.x) {
        const int eBase = tile * 128;
        const int ge = eBase + e_s;
        int u = 0, v = 0;
        if (ge < E) { u = eidx[ge]; v = eidx[E + ge]; }
        const float* zu  = z + (size_t)u * DIM;
        const float* zv  = z + (size_t)v * DIM;
        const float* abu = AB + (size_t)u * 256;
        const float* abv = AB + (size_t)v * 256 + 128;

        auto ld8 = [&](int c, float4* L) {
            const float4* pu = (const float4*)(zu  + c * 32 + q4 * 8);
            const float4* pv = (const float4*)(zv  + c * 32 + q4 * 8);
            const float4* pa = (const float4*)(abu + c * 32 + q4 * 8);
            const float4* pb = (const float4*)(abv + c * 32 + q4 * 8);
            L[0] = __ldg(pu); L[1] = __ldg(pu + 1);
            L[2] = __ldg(pv); L[3] = __ldg(pv + 1);
            L[4] = __ldg(pa); L[5] = __ldg(pa + 1);
            L[6] = __ldg(pb); L[7] = __ldg(pb + 1);
        };
        auto st8 = [&](int c, const float4* L) {
            unsigned char* fdst = smem + K2_SF + (c & 1) * 16384 + e_s * 128;
            int uu = q4 * 2;
            float4 d0, d1;
            d0.x = fabsf(L[0].x - L[2].x); d0.y = fabsf(L[0].y - L[2].y);
            d0.z = fabsf(L[0].z - L[2].z); d0.w = fabsf(L[0].w - L[2].w);
            d1.x = fabsf(L[1].x - L[3].x); d1.y = fabsf(L[1].y - L[3].y);
            d1.z = fabsf(L[1].z - L[3].z); d1.w = fabsf(L[1].w - L[3].w);
            *(float4*)(fdst + ((uu ^ e7x) << 4))       = tf4(d0);
            *(float4*)(fdst + (((uu + 1) ^ e7x) << 4)) = tf4(d1);
            float* sdst = sS + e_s * 132 + c * 32 + q4 * 8;
            float4 s0, s1;
            s0.x = L[4].x + L[6].x; s0.y = L[4].y + L[6].y;
            s0.z = L[4].z + L[6].z; s0.w = L[4].w + L[6].w;
            s1.x = L[5].x + L[7].x; s1.y = L[5].y + L[7].y;
            s1.z = L[5].z + L[7].z; s1.w = L[5].w + L[7].w;
            *(float4*)(sdst)     = s0;
            *(float4*)(sdst + 4) = s1;
        };

        { float4 L[8]; ld8(0, L); st8(0, L); }
        __syncthreads();

        float c[2][4][4];
        #pragma unroll
        for (int m = 0; m < 2; m++)
            #pragma unroll
            for (int n = 0; n < 4; n++)
                #pragma unroll
                for (int q = 0; q < 4; q++) c[m][n][q] = 0.f;

        #pragma unroll
        for (int ch = 0; ch < 4; ch++) {
            float4 L[8];
            if (ch < 3) ld8(ch + 1, L);                 // prefetch before MMA

            const uint32_t fbuf = sFb + (ch & 1) * 16384;
            #pragma unroll
            for (int ks = 0; ks < 4; ks++) {
                const int kk = ch * 4 + ks;
                const uint32_t swzA = (uint32_t)(((2 * ks + cselA) ^ l7)) << 4;
                const uint32_t swzB = (uint32_t)(((2 * kk + cselB) ^ l7)) << 4;
                uint32_t a[2][4];
                #pragma unroll
                for (int mt = 0; mt < 2; mt++)
                    ldsm4(a[mt][0], a[mt][1], a[mt][2], a[mt][3],
                          fbuf + (uint32_t)(32 * wy + 16 * mt + roffA + l7) * 128 + swzA);
                #pragma unroll
                for (int g = 0; g < 2; g++) {
                    uint32_t b[4];
                    ldsm4(b[0], b[1], b[2], b[3],
                          sWb + (uint32_t)(32 * wx + 16 * g + roffB + l7) * 512 + swzB);
                    #pragma unroll
                    for (int mt = 0; mt < 2; mt++) {
                        mma_tf32(c[mt][2*g  ][0], c[mt][2*g  ][1], c[mt][2*g  ][2], c[mt][2*g  ][3],
                                 a[mt][0], a[mt][1], a[mt][2], a[mt][3], b[0], b[1]);
                        mma_tf32(c[mt][2*g+1][0], c[mt][2*g+1][1], c[mt][2*g+1][2], c[mt][2*g+1][3],
                                 a[mt][0], a[mt][1], a[mt][2], a[mt][3], b[2], b[3]);
                    }
                }
            }
            if (ch < 3) st8(ch + 1, L);                 // store prefetch after MMA
            __syncthreads();
        }

        // epilogue
        float pe[2][2] = {{0.f, 0.f}, {0.f, 0.f}};
        #pragma unroll
        for (int mt = 0; mt < 2; mt++) {
            int e0 = 32 * wy + 16 * mt + gid;
            #pragma unroll
            for (int nt = 0; nt < 4; nt++) {
                int j = 32 * wx + 8 * nt + 2 * tig;
                const float* s0 = sS + e0 * 132 + j;
                const float* s1 = sS + (e0 + 8) * 132 + j;
                pe[mt][0] += fmaxf(c[mt][nt][0] + s0[0] + b1r[nt][0], 0.f) * w2r[nt][0]
                           + fmaxf(c[mt][nt][1] + s0[1] + b1r[nt][1], 0.f) * w2r[nt][1];
                pe[mt][1] += fmaxf(c[mt][nt][2] + s1[0] + b1r[nt][0], 0.f) * w2r[nt][0]
                           + fmaxf(c[mt][nt][3] + s1[1] + b1r[nt][1], 0.f) * w2r[nt][1];
            }
        }
        #pragma unroll
        for (int mt = 0; mt < 2; mt++)
            #pragma unroll
            for (int hh = 0; hh < 2; hh++) {
                float p = pe[mt][hh];
                p += __shfl_xor_sync(0xFFFFFFFFu, p, 1);
                p += __shfl_xor_sync(0xFFFFFFFFu, p, 2);
                if (tig == 0) sP[(32 * wy + 16 * mt + 8 * hh + gid) * 4 + wx] = p;
            }
        __syncthreads();

        if (tid < 128) {
            int g = eBase + tid;
            if (g < E)
                out[g] = sP[tid * 4] + sP[tid * 4 + 1] + sP[tid * 4 + 2] + sP[tid * 4 + 3] + bias2;
        }
        __syncthreads();   // sP/sS safe before next tile's staging
    }
}

extern "C" void kernel_launch(void* const* d_in, const int* in_sizes, int n_in,
                              void* d_out, int out_size) {
    const float* z    = (const float*)d_in[0];
    const int*   eidx = (const int*)d_in[1];   // int32 on the wire
    const float* W1   = (const float*)d_in[2];
    const float* b1   = (const float*)d_in[3];
    const float* W2   = (const float*)d_in[4];
    const float* b2   = (const float*)d_in[5];
    float*       out  = (float*)d_out;

    const int N = in_sizes[0] / DIM;           // 100000
    const int E = in_sizes[1] / 2;             // 500000
    const int t1 = (N + 127) / 128;            // 782
    const int t2 = (E + 127) / 128;            // 3907

    float* AB = nullptr;
    cudaGetSymbolAddress((void**)&AB, g_AB);

    const int k1_smem = 131072 + 32768;        // 163840
    cudaFuncSetAttribute(ab_gemm,  cudaFuncAttributeMaxDynamicSharedMemorySize, k1_smem);
    cudaFuncSetAttribute(edge_mlp, cudaFuncAttributeMaxDynamicSharedMemorySize, K2_SMEM);

    prep_w<<<192, 256>>>(W1);
    ab_gemm<<<148, 512, k1_smem>>>(z, AB, N, t1);
    edge_mlp<<<148, 512, K2_SMEM>>>(z, eidx, b1, W2, b2, AB, out, E, t2);
}

// round 10
// speedup vs baseline: 2.2730x; 1.2896x over previous
#include <cuda_runtime.h>
#include <cuda_fp16.h>
#include <cstdint>

// MLPDecoder, split + tf32 mma.sync; persistent W, 4-chunk double-buffered
// pipeline with register prefetch. Gathered operands stored fp16 (z copy + AB)
// to halve random-gather bytes and make the 77MB working set L2-resident.
//  prep: g_Wab[j][k]=tf32(W1ab^T), g_Wc[j][k]=tf32(W1c^T), g_zh=fp16(z)
//  k1:   AB[n][0:256] = [ z[n]@W1a , z[n]@W1b ]  (fp32 acc -> fp16 store)
//  k2:   C = |zu-zv| @ W1c; h = relu(C + ABu + ABv + b1); out = h@W2 + b2
// edge_index is int32 on the wire (JAX x64 disabled).

#define DIM 128
#define NMAX 100000

__device__ float  g_Wab[256 * 128];           // [j][k] tf32
__device__ float  g_Wc[128 * 128];            // [j][k] tf32
__device__ __half g_AB[(size_t)NMAX * 256];   // fp16
__device__ __half g_zh[(size_t)NMAX * 128];   // fp16 copy of z

__device__ __forceinline__ uint32_t f2tf(float x) {
    uint32_t r; asm("cvt.rna.tf32.f32 %0, %1;" : "=r"(r) : "f"(x)); return r;
}
__device__ __forceinline__ float tfpack(float x) { return __uint_as_float(f2tf(x)); }
__device__ __forceinline__ float4 tf4(float4 a) {
    float4 o; o.x = tfpack(a.x); o.y = tfpack(a.y); o.z = tfpack(a.z); o.w = tfpack(a.w);
    return o;
}
__device__ __forceinline__ void ldsm4(uint32_t& r0, uint32_t& r1, uint32_t& r2, uint32_t& r3,
                                      uint32_t addr) {
    asm volatile("ldmatrix.sync.aligned.m8n8.x4.shared.b16 {%0,%1,%2,%3}, [%4];"
                 : "=r"(r0), "=r"(r1), "=r"(r2), "=r"(r3) : "r"(addr));
}
__device__ __forceinline__ void mma_tf32(
    float& c0, float& c1, float& c2, float& c3,
    uint32_t a0, uint32_t a1, uint32_t a2, uint32_t a3,
    uint32_t b0, uint32_t b1)
{
    asm volatile(
        "mma.sync.aligned.m16n8k8.row.col.f32.tf32.tf32.f32 "
        "{%0,%1,%2,%3}, {%4,%5,%6,%7}, {%8,%9}, {%0,%1,%2,%3};"
        : "+f"(c0), "+f"(c1), "+f"(c2), "+f"(c3)
        : "r"(a0), "r"(a1), "r"(a2), "r"(a3), "r"(b0), "r"(b1));
}

// ---------------------------------------------------------------------------
__global__ void prep_w(const float* __restrict__ W1) {
    int i = blockIdx.x * 256 + threadIdx.x;
    if (i < 32768) {                       // Wab
        int j = i >> 7, k = i & 127;
        g_Wab[i] = tfpack(W1[(k + (j < 128 ? 0 : 128)) * 128 + (j & 127)]);
    } else if (i < 49152) {                // Wc
        int l = i - 32768;
        int j = l >> 7, k = l & 127;
        g_Wc[l] = tfpack(W1[(256 + k) * 128 + j]);
    }
}

__global__ void prep_z(const float* __restrict__ z, int n2) {
    int i = blockIdx.x * 512 + threadIdx.x;        // over n/2 float2 pairs
    if (i < n2) {
        float2 a = ((const float2*)z)[i];
        ((half2*)g_zh)[i] = __floats2half2_rn(a.x, a.y);
    }
}

// ---------------------------------------------------------------------------
// Kernel 1 (persistent): AB = z @ [W1a|W1b]. Tile 128r x 256c, K=128 in 4 chunks.
// 512 threads, warp tile 32r x 64c. smem: sW 131072 + sZ 2x16384 = 163840.
// ---------------------------------------------------------------------------
__global__ __launch_bounds__(512, 1) void ab_gemm(
    const float* __restrict__ z, __half* __restrict__ AB, int N, int ntiles)
{
    extern __shared__ __align__(16) unsigned char smem[];
    const int tid  = threadIdx.x;
    const int warp = tid >> 5;
    const int lane = tid & 31;
    const int wy = warp >> 2, wx = warp & 3;
    const int gid = lane >> 2, tig = lane & 3;

    #pragma unroll
    for (int p = 0; p < 16; p++) {
        int i = p * 512 + tid;
        int j = i >> 5, uu = i & 31;
        float4 w = __ldg((const float4*)g_Wab + (size_t)j * 32 + uu);
        *(float4*)(smem + j * 512 + ((uu ^ (j & 7)) << 4)) = w;
    }

    const uint32_t sWb = (uint32_t)__cvta_generic_to_shared(smem);
    const uint32_t sZb = sWb + 131072;
    const int l7 = lane & 7;
    const int roffA = ((lane >> 3) & 1) * 8, cselA = (lane >> 4) & 1;
    const int roffB = ((lane >> 4) & 1) * 8, cselB = (lane >> 3) & 1;

    const int r_s = tid & 127;
    const int q4  = tid >> 7;
    const int e7x = r_s & 7;
    __syncthreads();

    for (int tile = blockIdx.x; tile < ntiles; tile += gridDim.x) {
        const int rowBase = tile * 128;
        int zr = rowBase + r_s; if (zr >= N) zr = N - 1;
        const float* zrow = z + (size_t)zr * DIM;

        auto ld2 = [&](int c, float4& A0, float4& A1) {
            const float4* src = (const float4*)(zrow + c * 32 + q4 * 8);
            A0 = __ldg(src); A1 = __ldg(src + 1);
        };
        auto st2 = [&](int c, float4 A0, float4 A1) {
            unsigned char* dst = smem + 131072 + (c & 1) * 16384 + r_s * 128;
            int uu = q4 * 2;
            *(float4*)(dst + ((uu ^ e7x) << 4))       = tf4(A0);
            *(float4*)(dst + (((uu + 1) ^ e7x) << 4)) = tf4(A1);
        };

        { float4 A0, A1; ld2(0, A0, A1); st2(0, A0, A1); }
        __syncthreads();

        float c[2][8][4];
        #pragma unroll
        for (int m = 0; m < 2; m++)
            #pragma unroll
            for (int n = 0; n < 8; n++)
                #pragma unroll
                for (int q = 0; q < 4; q++) c[m][n][q] = 0.f;

        #pragma unroll
        for (int ch = 0; ch < 4; ch++) {
            float4 P0, P1;
            if (ch < 3) ld2(ch + 1, P0, P1);

            const uint32_t zbuf = sZb + (ch & 1) * 16384;
            #pragma unroll
            for (int ks = 0; ks < 4; ks++) {
                const int kk = ch * 4 + ks;
                const uint32_t swzA = (uint32_t)(((2 * ks + cselA) ^ l7)) << 4;
                const uint32_t swzB = (uint32_t)(((2 * kk + cselB) ^ l7)) << 4;
                uint32_t a[2][4];
                #pragma unroll
                for (int mt = 0; mt < 2; mt++)
                    ldsm4(a[mt][0], a[mt][1], a[mt][2], a[mt][3],
                          zbuf + (uint32_t)(32 * wy + 16 * mt + roffA + l7) * 128 + swzA);
                #pragma unroll
                for (int g = 0; g < 4; g++) {
                    uint32_t b[4];
                    ldsm4(b[0], b[1], b[2], b[3],
                          sWb + (uint32_t)(64 * wx + 16 * g + roffB + l7) * 512 + swzB);
                    #pragma unroll
                    for (int mt = 0; mt < 2; mt++) {
                        mma_tf32(c[mt][2*g  ][0], c[mt][2*g  ][1], c[mt][2*g  ][2], c[mt][2*g  ][3],
                                 a[mt][0], a[mt][1], a[mt][2], a[mt][3], b[0], b[1]);
                        mma_tf32(c[mt][2*g+1][0], c[mt][2*g+1][1], c[mt][2*g+1][2], c[mt][2*g+1][3],
                                 a[mt][0], a[mt][1], a[mt][2], a[mt][3], b[2], b[3]);
                    }
                }
            }
            if (ch < 3) st2(ch + 1, P0, P1);
            __syncthreads();
        }

        #pragma unroll
        for (int mt = 0; mt < 2; mt++) {
            int r0 = rowBase + 32 * wy + 16 * mt + gid;
            int r1 = r0 + 8;
            #pragma unroll
            for (int nt = 0; nt < 8; nt++) {
                int col = 64 * wx + 8 * nt + 2 * tig;
                if (r0 < N) *(half2*)(AB + (size_t)r0 * 256 + col) =
                    __floats2half2_rn(c[mt][nt][0], c[mt][nt][1]);
                if (r1 < N) *(half2*)(AB + (size_t)r1 * 256 + col) =
                    __floats2half2_rn(c[mt][nt][2], c[mt][nt][3]);
            }
        }
        __syncthreads();
    }
}

// ---------------------------------------------------------------------------
// Kernel 2 (persistent): C = |zu-zv| @ W1c (K=128, 4 chunks), fused MLP head.
// fp16 gathers: 4x LDG.128 per thread per chunk.
// ---------------------------------------------------------------------------
#define K2_SF   65536
#define K2_SS   98304
#define K2_SB1  165888
#define K2_SW2  166400
#define K2_SP   166912
#define K2_SMEM 168960

struct G4 { uint4 U, V, A, B; };

__global__ __launch_bounds__(512, 1) void edge_mlp(
    const __half* __restrict__ zh, const int* __restrict__ eidx,
    const float* __restrict__ b1, const float* __restrict__ W2,
    const float* __restrict__ b2, const __half* __restrict__ AB,
    float* __restrict__ out, int E, int ntiles)
{
    extern __shared__ __align__(16) unsigned char smem[];
    float* sS  = (float*)(smem + K2_SS);
    float* sb1 = (float*)(smem + K2_SB1);
    float* sw2 = (float*)(smem + K2_SW2);
    float* sP  = (float*)(smem + K2_SP);

    const int tid  = threadIdx.x;
    const int warp = tid >> 5;
    const int lane = tid & 31;
    const int wy = warp >> 2, wx = warp & 3;
    const int gid = lane >> 2, tig = lane & 3;

    if (tid < 128) { sb1[tid] = b1[tid]; sw2[tid] = W2[tid]; }

    #pragma unroll
    for (int p = 0; p < 8; p++) {
        int i = p * 512 + tid;
        int j = i >> 5, uu = i & 31;
        float4 w = __ldg((const float4*)g_Wc + (size_t)j * 32 + uu);
        *(float4*)(smem + j * 512 + ((uu ^ (j & 7)) << 4)) = w;
    }

    const uint32_t sWb = (uint32_t)__cvta_generic_to_shared(smem);
    const uint32_t sFb = sWb + K2_SF;
    const int l7 = lane & 7;
    const int roffA = ((lane >> 3) & 1) * 8, cselA = (lane >> 4) & 1;
    const int roffB = ((lane >> 4) & 1) * 8, cselB = (lane >> 3) & 1;

    const int e_s = tid & 127;
    const int q4  = tid >> 7;
    const int e7x = e_s & 7;
    const float bias2 = __ldg(b2);
    __syncthreads();

    float b1r[4][2], w2r[4][2];
    #pragma unroll
    for (int nt = 0; nt < 4; nt++) {
        int j = 32 * wx + 8 * nt + 2 * tig;
        b1r[nt][0] = sb1[j]; b1r[nt][1] = sb1[j + 1];
        w2r[nt][0] = sw2[j]; w2r[nt][1] = sw2[j + 1];
    }

    for (int tile = blockIdx.x; tile < ntiles; tile += gridDim.x) {
        const int eBase = tile * 128;
        const int ge = eBase + e_s;
        int u = 0, v = 0;
        if (ge < E) { u = eidx[ge]; v = eidx[E + ge]; }
        const __half* zu  = zh + (size_t)u * 128;
        const __half* zv  = zh + (size_t)v * 128;
        const __half* abu = AB + (size_t)u * 256;
        const __half* abv = AB + (size_t)v * 256 + 128;

        auto ld4 = [&](int c, G4& g) {
            g.U = __ldg((const uint4*)(zu  + c * 32 + q4 * 8));
            g.V = __ldg((const uint4*)(zv  + c * 32 + q4 * 8));
            g.A = __ldg((const uint4*)(abu + c * 32 + q4 * 8));
            g.B = __ldg((const uint4*)(abv + c * 32 + q4 * 8));
        };
        auto st4 = [&](int c, const G4& g) {
            const half2* up = (const half2*)&g.U;
            const half2* vp = (const half2*)&g.V;
            float2 u0 = __half22float2(up[0]), u1 = __half22float2(up[1]);
            float2 u2 = __half22float2(up[2]), u3 = __half22float2(up[3]);
            float2 v0 = __half22float2(vp[0]), v1 = __half22float2(vp[1]);
            float2 v2 = __half22float2(vp[2]), v3 = __half22float2(vp[3]);
            float4 d0, d1;
            d0.x = fabsf(u0.x - v0.x); d0.y = fabsf(u0.y - v0.y);
            d0.z = fabsf(u1.x - v1.x); d0.w = fabsf(u1.y - v1.y);
            d1.x = fabsf(u2.x - v2.x); d1.y = fabsf(u2.y - v2.y);
            d1.z = fabsf(u3.x - v3.x); d1.w = fabsf(u3.y - v3.y);
            unsigned char* fdst = smem + K2_SF + (c & 1) * 16384 + e_s * 128;
            int uu = q4 * 2;
            *(float4*)(fdst + ((uu ^ e7x) << 4))       = tf4(d0);
            *(float4*)(fdst + (((uu + 1) ^ e7x) << 4)) = tf4(d1);
            const half2* ap = (const half2*)&g.A;
            const half2* bp = (const half2*)&g.B;
            float2 a0 = __half22float2(ap[0]), a1 = __half22float2(ap[1]);
            float2 a2 = __half22float2(ap[2]), a3 = __half22float2(ap[3]);
            float2 b0 = __half22float2(bp[0]), b1v = __half22float2(bp[1]);
            float2 b2v = __half22float2(bp[2]), b3 = __half22float2(bp[3]);
            float* sdst = sS + e_s * 132 + c * 32 + q4 * 8;
            float4 s0, s1;
            s0.x = a0.x + b0.x;  s0.y = a0.y + b0.y;
            s0.z = a1.x + b1v.x; s0.w = a1.y + b1v.y;
            s1.x = a2.x + b2v.x; s1.y = a2.y + b2v.y;
            s1.z = a3.x + b3.x;  s1.w = a3.y + b3.y;
            *(float4*)(sdst)     = s0;
            *(float4*)(sdst + 4) = s1;
        };

        { G4 g; ld4(0, g); st4(0, g); }
        __syncthreads();

        float c[2][4][4];
        #pragma unroll
        for (int m = 0; m < 2; m++)
            #pragma unroll
            for (int n = 0; n < 4; n++)
                #pragma unroll
                for (int q = 0; q < 4; q++) c[m][n][q] = 0.f;

        #pragma unroll
        for (int ch = 0; ch < 4; ch++) {
            G4 g;
            if (ch < 3) ld4(ch + 1, g);                 // prefetch before MMA

            const uint32_t fbuf = sFb + (ch & 1) * 16384;
            #pragma unroll
            for (int ks = 0; ks < 4; ks++) {
                const int kk = ch * 4 + ks;
                const uint32_t swzA = (uint32_t)(((2 * ks + cselA) ^ l7)) << 4;
                const uint32_t swzB = (uint32_t)(((2 * kk + cselB) ^ l7)) << 4;
                uint32_t a[2][4];
                #pragma unroll
                for (int mt = 0; mt < 2; mt++)
                    ldsm4(a[mt][0], a[mt][1], a[mt][2], a[mt][3],
                          fbuf + (uint32_t)(32 * wy + 16 * mt + roffA + l7) * 128 + swzA);
                #pragma unroll
                for (int g2 = 0; g2 < 2; g2++) {
                    uint32_t b[4];
                    ldsm4(b[0], b[1], b[2], b[3],
                          sWb + (uint32_t)(32 * wx + 16 * g2 + roffB + l7) * 512 + swzB);
                    #pragma unroll
                    for (int mt = 0; mt < 2; mt++) {
                        mma_tf32(c[mt][2*g2  ][0], c[mt][2*g2  ][1], c[mt][2*g2  ][2], c[mt][2*g2  ][3],
                                 a[mt][0], a[mt][1], a[mt][2], a[mt][3], b[0], b[1]);
                        mma_tf32(c[mt][2*g2+1][0], c[mt][2*g2+1][1], c[mt][2*g2+1][2], c[mt][2*g2+1][3],
                                 a[mt][0], a[mt][1], a[mt][2], a[mt][3], b[2], b[3]);
                    }
                }
            }
            if (ch < 3) st4(ch + 1, g);                 // store prefetch after MMA
            __syncthreads();
        }

        // epilogue
        float pe[2][2] = {{0.f, 0.f}, {0.f, 0.f}};
        #pragma unroll
        for (int mt = 0; mt < 2; mt++) {
            int e0 = 32 * wy + 16 * mt + gid;
            #pragma unroll
            for (int nt = 0; nt < 4; nt++) {
                int j = 32 * wx + 8 * nt + 2 * tig;
                const float* s0 = sS + e0 * 132 + j;
                const float* s1 = sS + (e0 + 8) * 132 + j;
                pe[mt][0] += fmaxf(c[mt][nt][0] + s0[0] + b1r[nt][0], 0.f) * w2r[nt][0]
                           + fmaxf(c[mt][nt][1] + s0[1] + b1r[nt][1], 0.f) * w2r[nt][1];
                pe[mt][1] += fmaxf(c[mt][nt][2] + s1[0] + b1r[nt][0], 0.f) * w2r[nt][0]
                           + fmaxf(c[mt][nt][3] + s1[1] + b1r[nt][1], 0.f) * w2r[nt][1];
            }
        }
        #pragma unroll
        for (int mt = 0; mt < 2; mt++)
            #pragma unroll
            for (int hh = 0; hh < 2; hh++) {
                float p = pe[mt][hh];
                p += __shfl_xor_sync(0xFFFFFFFFu, p, 1);
                p += __shfl_xor_sync(0xFFFFFFFFu, p, 2);
                if (tig == 0) sP[(32 * wy + 16 * mt + 8 * hh + gid) * 4 + wx] = p;
            }
        __syncthreads();

        if (tid < 128) {
            int g = eBase + tid;
            if (g < E)
                out[g] = sP[tid * 4] + sP[tid * 4 + 1] + sP[tid * 4 + 2] + sP[tid * 4 + 3] + bias2;
        }
        __syncthreads();
    }
}

extern "C" void kernel_launch(void* const* d_in, const int* in_sizes, int n_in,
                              void* d_out, int out_size) {
    const float* z    = (const float*)d_in[0];
    const int*   eidx = (const int*)d_in[1];   // int32 on the wire
    const float* W1   = (const float*)d_in[2];
    const float* b1   = (const float*)d_in[3];
    const float* W2   = (const float*)d_in[4];
    const float* b2   = (const float*)d_in[5];
    float*       out  = (float*)d_out;

    const int N = in_sizes[0] / DIM;           // 100000
    const int E = in_sizes[1] / 2;             // 500000
    const int t1 = (N + 127) / 128;            // 782
    const int t2 = (E + 127) / 128;            // 3907

    __half* AB = nullptr; __half* ZH = nullptr;
    cudaGetSymbolAddress((void**)&AB, g_AB);
    cudaGetSymbolAddress((void**)&ZH, g_zh);

    const int k1_smem = 131072 + 32768;        // 163840
    cudaFuncSetAttribute(ab_gemm,  cudaFuncAttributeMaxDynamicSharedMemorySize, k1_smem);
    cudaFuncSetAttribute(edge_mlp, cudaFuncAttributeMaxDynamicSharedMemorySize, K2_SMEM);

    prep_w<<<192, 256>>>(W1);
    const int n2 = N * DIM / 2;                // 6.4M half2 pairs
    prep_z<<<(n2 + 511) / 512, 512>>>(z, n2);
    ab_gemm<<<148, 512, k1_smem>>>(z, AB, N, t1);
    edge_mlp<<<148, 512, K2_SMEM>>>(ZH, eidx, b1, W2, b2, AB, out, E, t2);
}

// round 11
// speedup vs baseline: 3.0708x; 1.3510x over previous
#include <cuda_runtime.h>
#include <cuda_fp16.h>
#include <cstdint>

// MLPDecoder, split + fp16 mma.sync (m16n8k16, fp32 accum); persistent, 2 CTAs/SM.
//  prep: g_Wab[j][k]=fp16(W1ab^T), g_Wc[j][k]=fp16(W1c^T), g_zh=fp16(z)
//  k1:   AB[n][0:256] = [ z[n]@W1a , z[n]@W1b ]  (fp16 in/out, fp32 acc)
//  k2:   C = |zu-zv| @ W1c; h = relu(C + ABu + ABv + b1); out = h@W2 + b2
// edge_index is int32 on the wire (JAX x64 disabled).

#define DIM 128
#define NMAX 100000

__device__ __half g_Wab[256 * 128];           // [j][k] fp16
__device__ __half g_Wc[128 * 128];            // [j][k] fp16
__device__ __half g_AB[(size_t)NMAX * 256];   // fp16
__device__ __half g_zh[(size_t)NMAX * 128];   // fp16 copy of z

__device__ __forceinline__ void ldsm4(uint32_t& r0, uint32_t& r1, uint32_t& r2, uint32_t& r3,
                                      uint32_t addr) {
    asm volatile("ldmatrix.sync.aligned.m8n8.x4.shared.b16 {%0,%1,%2,%3}, [%4];"
                 : "=r"(r0), "=r"(r1), "=r"(r2), "=r"(r3) : "r"(addr));
}
__device__ __forceinline__ void mma_f16(
    float& c0, float& c1, float& c2, float& c3,
    uint32_t a0, uint32_t a1, uint32_t a2, uint32_t a3,
    uint32_t b0, uint32_t b1)
{
    asm volatile(
        "mma.sync.aligned.m16n8k16.row.col.f32.f16.f16.f32 "
        "{%0,%1,%2,%3}, {%4,%5,%6,%7}, {%8,%9}, {%0,%1,%2,%3};"
        : "+f"(c0), "+f"(c1), "+f"(c2), "+f"(c3)
        : "r"(a0), "r"(a1), "r"(a2), "r"(a3), "r"(b0), "r"(b1));
}

// ---------------------------------------------------------------------------
__global__ void prep_w(const float* __restrict__ W1) {
    int i = blockIdx.x * 256 + threadIdx.x;
    if (i < 32768) {                       // Wab: [j 0..255][k 0..127]
        int j = i >> 7, k = i & 127;
        g_Wab[i] = __float2half_rn(W1[(k + (j < 128 ? 0 : 128)) * 128 + (j & 127)]);
    } else if (i < 49152) {                // Wc: [j 0..127][k 0..127]
        int l = i - 32768;
        int j = l >> 7, k = l & 127;
        g_Wc[l] = __float2half_rn(W1[(256 + k) * 128 + j]);
    }
}

__global__ void prep_z(const float* __restrict__ z, int n2) {
    int i = blockIdx.x * 512 + threadIdx.x;
    if (i < n2) {
        float2 a = ((const float2*)z)[i];
        ((half2*)g_zh)[i] = __floats2half2_rn(a.x, a.y);
    }
}

// ---------------------------------------------------------------------------
// Kernel 1: AB = z @ [W1a|W1b]. Tile 64r x 256c, K=128 (4 chunks of 32).
// 256 threads (2 CTAs/SM), warp tile 32r x 64c.
// smem: sW [256j][128k fp16, 256B swz rows] 65536 + sZ 2 x (64r x 128B) 16384.
// ---------------------------------------------------------------------------
__global__ __launch_bounds__(256, 2) void ab_gemm(
    const __half* __restrict__ zh, __half* __restrict__ AB, int N, int ntiles)
{
    extern __shared__ __align__(16) unsigned char smem[];
    const int tid  = threadIdx.x;
    const int warp = tid >> 5;
    const int lane = tid & 31;
    const int wy = warp >> 2, wx = warp & 3;
    const int gid = lane >> 2, tig = lane & 3;
    const int l7 = lane & 7;

    // stage W once: 4096 uint4 (rows 256B, XOR-swizzled 16B units)
    #pragma unroll
    for (int p = 0; p < 16; p++) {
        int i = p * 256 + tid;
        int j = i >> 4, uu = i & 15;
        uint4 w = __ldg((const uint4*)g_Wab + (size_t)j * 16 + uu);
        *(uint4*)(smem + j * 256 + ((uu ^ (j & 7)) << 4)) = w;
    }

    const uint32_t sWb = (uint32_t)__cvta_generic_to_shared(smem);
    const uint32_t sZb = sWb + 65536;
    const int rA = lane & 15;           // A ldsm row within m16 tile
    const int cA = lane >> 4;           // A k-half select
    const int rBoff = ((lane >> 4) & 1) * 8 + l7;   // B row offset within n16 group
    const int cB = (lane >> 3) & 1;                  // B k-half select

    const int r_s = tid & 63;
    const int q4  = tid >> 6;           // 0..3 -> 8 halves of the 32-half chunk
    const int e7  = r_s & 7;
    __syncthreads();

    for (int tile = blockIdx.x; tile < ntiles; tile += gridDim.x) {
        const int rowBase = tile * 64;
        int zr = rowBase + r_s; if (zr >= N) zr = N - 1;
        const __half* zrow = zh + (size_t)zr * 128;

        auto ld1 = [&](int c) -> uint4 {
            return __ldg((const uint4*)(zrow + c * 32 + q4 * 8));
        };
        auto st1 = [&](int c, uint4 Z) {
            *(uint4*)(smem + 65536 + (c & 1) * 8192 + r_s * 128 + ((q4 ^ e7) << 4)) = Z;
        };

        st1(0, ld1(0));
        __syncthreads();

        float c[2][8][4];
        #pragma unroll
        for (int m = 0; m < 2; m++)
            #pragma unroll
            for (int n = 0; n < 8; n++)
                #pragma unroll
                for (int q = 0; q < 4; q++) c[m][n][q] = 0.f;

        #pragma unroll
        for (int ch = 0; ch < 4; ch++) {
            uint4 P;
            if (ch < 3) P = ld1(ch + 1);

            const uint32_t zbuf = sZb + (ch & 1) * 8192;
            #pragma unroll
            for (int ks = 0; ks < 2; ks++) {
                const int kk = ch * 2 + ks;
                uint32_t a[2][4];
                #pragma unroll
                for (int mt = 0; mt < 2; mt++)
                    ldsm4(a[mt][0], a[mt][1], a[mt][2], a[mt][3],
                          zbuf + (uint32_t)(32 * wy + 16 * mt + rA) * 128
                               + (uint32_t)(((ks * 2 + cA) ^ l7) << 4));
                #pragma unroll
                for (int g = 0; g < 4; g++) {
                    uint32_t b[4];
                    ldsm4(b[0], b[1], b[2], b[3],
                          sWb + (uint32_t)(64 * wx + 16 * g + rBoff) * 256
                              + (uint32_t)(((kk * 2 + cB) ^ l7) << 4));
                    #pragma unroll
                    for (int mt = 0; mt < 2; mt++) {
                        mma_f16(c[mt][2*g  ][0], c[mt][2*g  ][1], c[mt][2*g  ][2], c[mt][2*g  ][3],
                                a[mt][0], a[mt][1], a[mt][2], a[mt][3], b[0], b[1]);
                        mma_f16(c[mt][2*g+1][0], c[mt][2*g+1][1], c[mt][2*g+1][2], c[mt][2*g+1][3],
                                a[mt][0], a[mt][1], a[mt][2], a[mt][3], b[2], b[3]);
                    }
                }
            }
            if (ch < 3) st1(ch + 1, P);
            __syncthreads();
        }

        #pragma unroll
        for (int mt = 0; mt < 2; mt++) {
            int r0 = rowBase + 32 * wy + 16 * mt + gid;
            int r1 = r0 + 8;
            #pragma unroll
            for (int nt = 0; nt < 8; nt++) {
                int col = 64 * wx + 8 * nt + 2 * tig;
                if (r0 < N) *(half2*)(AB + (size_t)r0 * 256 + col) =
                    __floats2half2_rn(c[mt][nt][0], c[mt][nt][1]);
                if (r1 < N) *(half2*)(AB + (size_t)r1 * 256 + col) =
                    __floats2half2_rn(c[mt][nt][2], c[mt][nt][3]);
            }
        }
        __syncthreads();
    }
}

// ---------------------------------------------------------------------------
// Kernel 2: per 64-edge tile, C = |zu-zv| @ W1c (K=128, 4 chunks), fused head.
// 256 threads (2 CTAs/SM), warp tile 32e x 32j.
// smem: sW 32768 + sF 2x8192 + sS[64][132] fp32 33792 + b1/w2 1024 + sP 1024.
// ---------------------------------------------------------------------------
#define K2_SF   32768
#define K2_SS   49152
#define K2_SB1  82944
#define K2_SW2  83456
#define K2_SP   83968
#define K2_SMEM 84992

struct G4 { uint4 U, V, A, B; };

__global__ __launch_bounds__(256, 2) void edge_mlp(
    const __half* __restrict__ zh, const int* __restrict__ eidx,
    const float* __restrict__ b1, const float* __restrict__ W2,
    const float* __restrict__ b2, const __half* __restrict__ AB,
    float* __restrict__ out, int E, int ntiles)
{
    extern __shared__ __align__(16) unsigned char smem[];
    float* sS  = (float*)(smem + K2_SS);
    float* sb1 = (float*)(smem + K2_SB1);
    float* sw2 = (float*)(smem + K2_SW2);
    float* sP  = (float*)(smem + K2_SP);

    const int tid  = threadIdx.x;
    const int warp = tid >> 5;
    const int lane = tid & 31;
    const int wy = warp >> 2, wx = warp & 3;
    const int gid = lane >> 2, tig = lane & 3;
    const int l7 = lane & 7;

    if (tid < 128) { sb1[tid] = b1[tid]; sw2[tid] = W2[tid]; }

    // stage W1c once: 2048 uint4
    #pragma unroll
    for (int p = 0; p < 8; p++) {
        int i = p * 256 + tid;
        int j = i >> 4, uu = i & 15;
        uint4 w = __ldg((const uint4*)g_Wc + (size_t)j * 16 + uu);
        *(uint4*)(smem + j * 256 + ((uu ^ (j & 7)) << 4)) = w;
    }

    const uint32_t sWb = (uint32_t)__cvta_generic_to_shared(smem);
    const uint32_t sFb = sWb + K2_SF;
    const int rA = lane & 15;
    const int cA = lane >> 4;
    const int rBoff = ((lane >> 4) & 1) * 8 + l7;
    const int cB = (lane >> 3) & 1;

    const int e_s = tid & 63;
    const int q4  = tid >> 6;
    const int e7  = e_s & 7;
    const float bias2 = __ldg(b2);
    __syncthreads();

    float b1r[4][2], w2r[4][2];
    #pragma unroll
    for (int nt = 0; nt < 4; nt++) {
        int j = 32 * wx + 8 * nt + 2 * tig;
        b1r[nt][0] = sb1[j]; b1r[nt][1] = sb1[j + 1];
        w2r[nt][0] = sw2[j]; w2r[nt][1] = sw2[j + 1];
    }

    for (int tile = blockIdx.x; tile < ntiles; tile += gridDim.x) {
        const int eBase = tile * 64;
        const int ge = eBase + e_s;
        int u = 0, v = 0;
        if (ge < E) { u = eidx[ge]; v = eidx[E + ge]; }
        const __half* zu  = zh + (size_t)u * 128;
        const __half* zv  = zh + (size_t)v * 128;
        const __half* abu = AB + (size_t)u * 256;
        const __half* abv = AB + (size_t)v * 256 + 128;

        auto ld4 = [&](int c, G4& g) {
            g.U = __ldg((const uint4*)(zu  + c * 32 + q4 * 8));
            g.V = __ldg((const uint4*)(zv  + c * 32 + q4 * 8));
            g.A = __ldg((const uint4*)(abu + c * 32 + q4 * 8));
            g.B = __ldg((const uint4*)(abv + c * 32 + q4 * 8));
        };
        auto st4 = [&](int c, const G4& g) {
            const half2* up = (const half2*)&g.U;
            const half2* vp = (const half2*)&g.V;
            uint4 D;
            half2* dp = (half2*)&D;
            #pragma unroll
            for (int i = 0; i < 4; i++) dp[i] = __habs2(__hsub2(up[i], vp[i]));
            *(uint4*)(smem + K2_SF + (c & 1) * 8192 + e_s * 128 + ((q4 ^ e7) << 4)) = D;

            const half2* ap = (const half2*)&g.A;
            const half2* bp = (const half2*)&g.B;
            float* sdst = sS + e_s * 132 + c * 32 + q4 * 8;
            #pragma unroll
            for (int i = 0; i < 4; i++) {
                float2 a = __half22float2(ap[i]);
                float2 b = __half22float2(bp[i]);
                sdst[2 * i]     = a.x + b.x;
                sdst[2 * i + 1] = a.y + b.y;
            }
        };

        { G4 g; ld4(0, g); st4(0, g); }
        __syncthreads();

        float c[2][4][4];
        #pragma unroll
        for (int m = 0; m < 2; m++)
            #pragma unroll
            for (int n = 0; n < 4; n++)
                #pragma unroll
                for (int q = 0; q < 4; q++) c[m][n][q] = 0.f;

        #pragma unroll
        for (int ch = 0; ch < 4; ch++) {
            G4 g;
            if (ch < 3) ld4(ch + 1, g);

            const uint32_t fbuf = sFb + (ch & 1) * 8192;
            #pragma unroll
            for (int ks = 0; ks < 2; ks++) {
                const int kk = ch * 2 + ks;
                uint32_t a[2][4];
                #pragma unroll
                for (int mt = 0; mt < 2; mt++)
                    ldsm4(a[mt][0], a[mt][1], a[mt][2], a[mt][3],
                          fbuf + (uint32_t)(32 * wy + 16 * mt + rA) * 128
                               + (uint32_t)(((ks * 2 + cA) ^ l7) << 4));
                #pragma unroll
                for (int g2 = 0; g2 < 2; g2++) {
                    uint32_t b[4];
                    ldsm4(b[0], b[1], b[2], b[3],
                          sWb + (uint32_t)(32 * wx + 16 * g2 + rBoff) * 256
                              + (uint32_t)(((kk * 2 + cB) ^ l7) << 4));
                    #pragma unroll
                    for (int mt = 0; mt < 2; mt++) {
                        mma_f16(c[mt][2*g2  ][0], c[mt][2*g2  ][1], c[mt][2*g2  ][2], c[mt][2*g2  ][3],
                                a[mt][0], a[mt][1], a[mt][2], a[mt][3], b[0], b[1]);
                        mma_f16(c[mt][2*g2+1][0], c[mt][2*g2+1][1], c[mt][2*g2+1][2], c[mt][2*g2+1][3],
                                a[mt][0], a[mt][1], a[mt][2], a[mt][3], b[2], b[3]);
                    }
                }
            }
            if (ch < 3) st4(ch + 1, g);
            __syncthreads();
        }

        // epilogue
        float pe[2][2] = {{0.f, 0.f}, {0.f, 0.f}};
        #pragma unroll
        for (int mt = 0; mt < 2; mt++) {
            int e0 = 32 * wy + 16 * mt + gid;
            #pragma unroll
            for (int nt = 0; nt < 4; nt++) {
                int j = 32 * wx + 8 * nt + 2 * tig;
                const float* s0 = sS + e0 * 132 + j;
                const float* s1 = sS + (e0 + 8) * 132 + j;
                pe[mt][0] += fmaxf(c[mt][nt][0] + s0[0] + b1r[nt][0], 0.f) * w2r[nt][0]
                           + fmaxf(c[mt][nt][1] + s0[1] + b1r[nt][1], 0.f) * w2r[nt][1];
                pe[mt][1] += fmaxf(c[mt][nt][2] + s1[0] + b1r[nt][0], 0.f) * w2r[nt][0]
                           + fmaxf(c[mt][nt][3] + s1[1] + b1r[nt][1], 0.f) * w2r[nt][1];
            }
        }
        #pragma unroll
        for (int mt = 0; mt < 2; mt++)
            #pragma unroll
            for (int hh = 0; hh < 2; hh++) {
                float p = pe[mt][hh];
                p += __shfl_xor_sync(0xFFFFFFFFu, p, 1);
                p += __shfl_xor_sync(0xFFFFFFFFu, p, 2);
                if (tig == 0) sP[(32 * wy + 16 * mt + 8 * hh + gid) * 4 + wx] = p;
            }
        __syncthreads();

        if (tid < 64) {
            int g = eBase + tid;
            if (g < E)
                out[g] = sP[tid * 4] + sP[tid * 4 + 1] + sP[tid * 4 + 2] + sP[tid * 4 + 3] + bias2;
        }
        __syncthreads();
    }
}

extern "C" void kernel_launch(void* const* d_in, const int* in_sizes, int n_in,
                              void* d_out, int out_size) {
    const float* z    = (const float*)d_in[0];
    const int*   eidx = (const int*)d_in[1];   // int32 on the wire
    const float* W1   = (const float*)d_in[2];
    const float* b1   = (const float*)d_in[3];
    const float* W2   = (const float*)d_in[4];
    const float* b2   = (const float*)d_in[5];
    float*       out  = (float*)d_out;

    const int N = in_sizes[0] / DIM;           // 100000
    const int E = in_sizes[1] / 2;             // 500000
    const int t1 = (N + 63) / 64;              // 1563
    const int t2 = (E + 63) / 64;              // 7813

    __half* AB = nullptr; __half* ZH = nullptr;
    cudaGetSymbolAddress((void**)&AB, g_AB);
    cudaGetSymbolAddress((void**)&ZH, g_zh);

    const int k1_smem = 65536 + 16384;         // 81920
    cudaFuncSetAttribute(ab_gemm,  cudaFuncAttributeMaxDynamicSharedMemorySize, k1_smem);
    cudaFuncSetAttribute(edge_mlp, cudaFuncAttributeMaxDynamicSharedMemorySize, K2_SMEM);

    prep_w<<<192, 256>>>(W1);
    const int n2 = N * DIM / 2;
    prep_z<<<(n2 + 511) / 512, 512>>>(z, n2);
    ab_gemm<<<296, 256, k1_smem>>>(ZH, AB, N, t1);
    edge_mlp<<<296, 256, K2_SMEM>>>(ZH, eidx, b1, W2, b2, AB, out, E, t2);
}

// round 12
// speedup vs baseline: 5.0166x; 1.6337x over previous
#include <cuda_runtime.h>
#include <cuda_fp16.h>
#include <cstdint>

// MLPDecoder, split + fp16 mma.sync (m16n8k16, fp32 accum); persistent, 2 CTAs/SM.
// R12: coalesced gathers (16 lanes per edge row) + cross-tile double buffering.
//  prep: g_Wab[j][k]=fp16(W1ab^T), g_Wc[j][k]=fp16(W1c^T), g_zh=fp16(z)
//  k1:   AB[n][0:256] = [ z[n]@W1a , z[n]@W1b ]
//  k2:   C = |zu-zv| @ W1c; h = relu(C + ABu + ABv + b1); out = h@W2 + b2
// edge_index is int32 on the wire (JAX x64 disabled).

#define DIM 128
#define NMAX 100000

__device__ __half g_Wab[256 * 128];           // [j][k] fp16
__device__ __half g_Wc[128 * 128];            // [j][k] fp16
__device__ __half g_AB[(size_t)NMAX * 256];   // fp16
__device__ __half g_zh[(size_t)NMAX * 128];   // fp16 copy of z

__device__ __forceinline__ void ldsm4(uint32_t& r0, uint32_t& r1, uint32_t& r2, uint32_t& r3,
                                      uint32_t addr) {
    asm volatile("ldmatrix.sync.aligned.m8n8.x4.shared.b16 {%0,%1,%2,%3}, [%4];"
                 : "=r"(r0), "=r"(r1), "=r"(r2), "=r"(r3) : "r"(addr));
}
__device__ __forceinline__ void mma_f16(
    float& c0, float& c1, float& c2, float& c3,
    uint32_t a0, uint32_t a1, uint32_t a2, uint32_t a3,
    uint32_t b0, uint32_t b1)
{
    asm volatile(
        "mma.sync.aligned.m16n8k16.row.col.f32.f16.f16.f32 "
        "{%0,%1,%2,%3}, {%4,%5,%6,%7}, {%8,%9}, {%0,%1,%2,%3};"
        : "+f"(c0), "+f"(c1), "+f"(c2), "+f"(c3)
        : "r"(a0), "r"(a1), "r"(a2), "r"(a3), "r"(b0), "r"(b1));
}

// ---------------------------------------------------------------------------
__global__ void prep_w(const float* __restrict__ W1) {
    int i = blockIdx.x * 256 + threadIdx.x;
    if (i < 32768) {
        int j = i >> 7, k = i & 127;
        g_Wab[i] = __float2half_rn(W1[(k + (j < 128 ? 0 : 128)) * 128 + (j & 127)]);
    } else if (i < 49152) {
        int l = i - 32768;
        int j = l >> 7, k = l & 127;
        g_Wc[l] = __float2half_rn(W1[(256 + k) * 128 + j]);
    }
}

__global__ void prep_z(const float* __restrict__ z, int n2) {
    int i = blockIdx.x * 512 + threadIdx.x;
    if (i < n2) {
        float2 a = ((const float2*)z)[i];
        ((half2*)g_zh)[i] = __floats2half2_rn(a.x, a.y);
    }
}

// ---------------------------------------------------------------------------
// Kernel 1 (unchanged from R11): AB = z @ [W1a|W1b]. 64r x 256c tiles, K=128.
// ---------------------------------------------------------------------------
__global__ __launch_bounds__(256, 2) void ab_gemm(
    const __half* __restrict__ zh, __half* __restrict__ AB, int N, int ntiles)
{
    extern __shared__ __align__(16) unsigned char smem[];
    const int tid  = threadIdx.x;
    const int warp = tid >> 5;
    const int lane = tid & 31;
    const int wy = warp >> 2, wx = warp & 3;
    const int gid = lane >> 2, tig = lane & 3;
    const int l7 = lane & 7;

    #pragma unroll
    for (int p = 0; p < 16; p++) {
        int i = p * 256 + tid;
        int j = i >> 4, uu = i & 15;
        uint4 w = __ldg((const uint4*)g_Wab + (size_t)j * 16 + uu);
        *(uint4*)(smem + j * 256 + ((uu ^ (j & 7)) << 4)) = w;
    }

    const uint32_t sWb = (uint32_t)__cvta_generic_to_shared(smem);
    const uint32_t sZb = sWb + 65536;
    const int rA = lane & 15;
    const int cA = lane >> 4;
    const int rBoff = ((lane >> 4) & 1) * 8 + l7;
    const int cB = (lane >> 3) & 1;

    const int r_s = tid & 63;
    const int q4  = tid >> 6;
    const int e7  = r_s & 7;
    __syncthreads();

    for (int tile = blockIdx.x; tile < ntiles; tile += gridDim.x) {
        const int rowBase = tile * 64;
        int zr = rowBase + r_s; if (zr >= N) zr = N - 1;
        const __half* zrow = zh + (size_t)zr * 128;

        auto ld1 = [&](int c) -> uint4 {
            return __ldg((const uint4*)(zrow + c * 32 + q4 * 8));
        };
        auto st1 = [&](int c, uint4 Z) {
            *(uint4*)(smem + 65536 + (c & 1) * 8192 + r_s * 128 + ((q4 ^ e7) << 4)) = Z;
        };

        st1(0, ld1(0));
        __syncthreads();

        float c[2][8][4];
        #pragma unroll
        for (int m = 0; m < 2; m++)
            #pragma unroll
            for (int n = 0; n < 8; n++)
                #pragma unroll
                for (int q = 0; q < 4; q++) c[m][n][q] = 0.f;

        #pragma unroll
        for (int ch = 0; ch < 4; ch++) {
            uint4 P;
            if (ch < 3) P = ld1(ch + 1);

            const uint32_t zbuf = sZb + (ch & 1) * 8192;
            #pragma unroll
            for (int ks = 0; ks < 2; ks++) {
                const int kk = ch * 2 + ks;
                uint32_t a[2][4];
                #pragma unroll
                for (int mt = 0; mt < 2; mt++)
                    ldsm4(a[mt][0], a[mt][1], a[mt][2], a[mt][3],
                          zbuf + (uint32_t)(32 * wy + 16 * mt + rA) * 128
                               + (uint32_t)(((ks * 2 + cA) ^ l7) << 4));
                #pragma unroll
                for (int g = 0; g < 4; g++) {
                    uint32_t b[4];
                    ldsm4(b[0], b[1], b[2], b[3],
                          sWb + (uint32_t)(64 * wx + 16 * g + rBoff) * 256
                              + (uint32_t)(((kk * 2 + cB) ^ l7) << 4));
                    #pragma unroll
                    for (int mt = 0; mt < 2; mt++) {
                        mma_f16(c[mt][2*g  ][0], c[mt][2*g  ][1], c[mt][2*g  ][2], c[mt][2*g  ][3],
                                a[mt][0], a[mt][1], a[mt][2], a[mt][3], b[0], b[1]);
                        mma_f16(c[mt][2*g+1][0], c[mt][2*g+1][1], c[mt][2*g+1][2], c[mt][2*g+1][3],
                                a[mt][0], a[mt][1], a[mt][2], a[mt][3], b[2], b[3]);
                    }
                }
            }
            if (ch < 3) st1(ch + 1, P);
            __syncthreads();
        }

        #pragma unroll
        for (int mt = 0; mt < 2; mt++) {
            int r0 = rowBase + 32 * wy + 16 * mt + gid;
            int r1 = r0 + 8;
            #pragma unroll
            for (int nt = 0; nt < 8; nt++) {
                int col = 64 * wx + 8 * nt + 2 * tig;
                if (r0 < N) *(half2*)(AB + (size_t)r0 * 256 + col) =
                    __floats2half2_rn(c[mt][nt][0], c[mt][nt][1]);
                if (r1 < N) *(half2*)(AB + (size_t)r1 * 256 + col) =
                    __floats2half2_rn(c[mt][nt][2], c[mt][nt][3]);
            }
        }
        __syncthreads();
    }
}

// ---------------------------------------------------------------------------
// Kernel 2 (R12): 64-edge tiles; COALESCED gathers (16 lanes per edge row);
// cross-tile double buffering: while MMAing tile t, stage tile t+grid.
// smem: sW 32768 + sF 2x16384 (64e x 256B swz) + sS16 2x17408 (64e x 272B fp16)
//       + b1 512 + w2 512 + sP 1024 = 102400 B -> 2 CTAs/SM.
// ---------------------------------------------------------------------------
#define K2_SF   32768
#define K2_SS   65536
#define K2_SB1  100352
#define K2_SW2  100864
#define K2_SP   101376
#define K2_SMEM 102400

struct G4 { uint4 U, V, A, B; };

__global__ __launch_bounds__(256, 2) void edge_mlp(
    const __half* __restrict__ zh, const int* __restrict__ eidx,
    const float* __restrict__ b1, const float* __restrict__ W2,
    const float* __restrict__ b2, const __half* __restrict__ AB,
    float* __restrict__ out, int E, int ntiles)
{
    extern __shared__ __align__(16) unsigned char smem[];
    float* sb1 = (float*)(smem + K2_SB1);
    float* sw2 = (float*)(smem + K2_SW2);
    float* sP  = (float*)(smem + K2_SP);

    const int tid  = threadIdx.x;
    const int warp = tid >> 5;
    const int lane = tid & 31;
    const int wy = warp >> 2, wx = warp & 3;
    const int gid = lane >> 2, tig = lane & 3;
    const int l7 = lane & 7;

    if (tid < 128) { sb1[tid] = b1[tid]; sw2[tid] = W2[tid]; }

    // stage W1c once: rows 256B, XOR-swizzled
    #pragma unroll
    for (int p = 0; p < 8; p++) {
        int i = p * 256 + tid;
        int j = i >> 4, uu = i & 15;
        uint4 w = __ldg((const uint4*)g_Wc + (size_t)j * 16 + uu);
        *(uint4*)(smem + j * 256 + ((uu ^ (j & 7)) << 4)) = w;
    }

    const uint32_t sWb = (uint32_t)__cvta_generic_to_shared(smem);
    const uint32_t sFb = sWb + K2_SF;
    const int rA = lane & 15;
    const int cA = lane >> 4;
    const int rBoff = ((lane >> 4) & 1) * 8 + l7;
    const int cB = (lane >> 3) & 1;

    // gather mapping: this lane serves edge (pass*16 + warp*2 + eh), 16B unit u16
    const int eh  = lane >> 4;          // 0/1: which of the warp's 2 edges
    const int u16 = lane & 15;          // 16B unit within 256B row
    const float bias2 = __ldg(b2);
    __syncthreads();

    float b1r[4][2], w2r[4][2];
    #pragma unroll
    for (int nt = 0; nt < 4; nt++) {
        int j = 32 * wx + 8 * nt + 2 * tig;
        b1r[nt][0] = sb1[j]; b1r[nt][1] = sb1[j + 1];
        w2r[nt][0] = sw2[j]; w2r[nt][1] = sw2[j + 1];
    }

    // load pass p of tile with base 'base' into registers
    auto ld_pass = [&](int p, int base, G4& g) {
        int e_loc = p * 16 + warp * 2 + eh;
        int ge = base + e_loc;
        int u = 0, v = 0;
        if (ge < E) { u = eidx[ge]; v = eidx[E + ge]; }
        g.U = __ldg((const uint4*)(zh + (size_t)u * 128) + u16);
        g.V = __ldg((const uint4*)(zh + (size_t)v * 128) + u16);
        g.A = __ldg((const uint4*)(AB + (size_t)u * 256) + u16);
        g.B = __ldg((const uint4*)(AB + (size_t)v * 256 + 128) + u16);
    };
    // convert + store pass p into buffer nb
    auto st_pass = [&](int p, const G4& g, int nb) {
        int e_loc = p * 16 + warp * 2 + eh;
        const half2* up = (const half2*)&g.U;
        const half2* vp = (const half2*)&g.V;
        uint4 D; half2* dp = (half2*)&D;
        #pragma unroll
        for (int i = 0; i < 4; i++) dp[i] = __habs2(__hsub2(up[i], vp[i]));
        *(uint4*)(smem + K2_SF + nb * 16384 + e_loc * 256 + ((u16 ^ (e_loc & 7)) << 4)) = D;
        const half2* ap = (const half2*)&g.A;
        const half2* bp = (const half2*)&g.B;
        uint4 S; half2* sp = (half2*)&S;
        #pragma unroll
        for (int i = 0; i < 4; i++) sp[i] = __hadd2(ap[i], bp[i]);
        *(uint4*)(smem + K2_SS + nb * 17408 + e_loc * 272 + u16 * 16) = S;
    };

    // prologue: stage this CTA's first tile into buffer 0
    int tile = blockIdx.x;
    if (tile < ntiles) {
        #pragma unroll
        for (int p = 0; p < 4; p++) { G4 g; ld_pass(p, tile * 64, g); st_pass(p, g, 0); }
    }
    __syncthreads();

    int cur = 0;
    for (; tile < ntiles; tile += gridDim.x) {
        const int eBase = tile * 64;
        const int nxt = tile + gridDim.x;
        const bool hasNext = nxt < ntiles;
        const uint32_t fbuf = sFb + cur * 16384;
        const __half* sS16 = (const __half*)(smem + K2_SS + cur * 17408);

        float c[2][4][4];
        #pragma unroll
        for (int m = 0; m < 2; m++)
            #pragma unroll
            for (int n = 0; n < 4; n++)
                #pragma unroll
                for (int q = 0; q < 4; q++) c[m][n][q] = 0.f;

        // 4 passes: load next-tile pass -> 2 MMA k-steps -> store pass
        #pragma unroll
        for (int p = 0; p < 4; p++) {
            G4 g;
            if (hasNext) ld_pass(p, nxt * 64, g);
            #pragma unroll
            for (int ks2 = 0; ks2 < 2; ks2++) {
                const int kk = p * 2 + ks2;      // global k-step 0..7
                uint32_t a[2][4];
                #pragma unroll
                for (int mt = 0; mt < 2; mt++)
                    ldsm4(a[mt][0], a[mt][1], a[mt][2], a[mt][3],
                          fbuf + (uint32_t)(32 * wy + 16 * mt + rA) * 256
                               + (uint32_t)(((kk * 2 + cA) ^ l7) << 4));
                #pragma unroll
                for (int g2 = 0; g2 < 2; g2++) {
                    uint32_t b[4];
                    ldsm4(b[0], b[1], b[2], b[3],
                          sWb + (uint32_t)(32 * wx + 16 * g2 + rBoff) * 256
                              + (uint32_t)(((kk * 2 + cB) ^ l7) << 4));
                    #pragma unroll
                    for (int mt = 0; mt < 2; mt++) {
                        mma_f16(c[mt][2*g2  ][0], c[mt][2*g2  ][1], c[mt][2*g2  ][2], c[mt][2*g2  ][3],
                                a[mt][0], a[mt][1], a[mt][2], a[mt][3], b[0], b[1]);
                        mma_f16(c[mt][2*g2+1][0], c[mt][2*g2+1][1], c[mt][2*g2+1][2], c[mt][2*g2+1][3],
                                a[mt][0], a[mt][1], a[mt][2], a[mt][3], b[2], b[3]);
                    }
                }
            }
            if (hasNext) st_pass(p, g, cur ^ 1);
        }

        // epilogue: h = relu(C + S + b1); partial = h . W2
        float pe[2][2] = {{0.f, 0.f}, {0.f, 0.f}};
        #pragma unroll
        for (int mt = 0; mt < 2; mt++) {
            int e0 = 32 * wy + 16 * mt + gid;
            #pragma unroll
            for (int nt = 0; nt < 4; nt++) {
                int j = 32 * wx + 8 * nt + 2 * tig;
                float2 s0 = __half22float2(*(const half2*)(sS16 + e0 * 136 + j));
                float2 s1 = __half22float2(*(const half2*)(sS16 + (e0 + 8) * 136 + j));
                pe[mt][0] += fmaxf(c[mt][nt][0] + s0.x + b1r[nt][0], 0.f) * w2r[nt][0]
                           + fmaxf(c[mt][nt][1] + s0.y + b1r[nt][1], 0.f) * w2r[nt][1];
                pe[mt][1] += fmaxf(c[mt][nt][2] + s1.x + b1r[nt][0], 0.f) * w2r[nt][0]
                           + fmaxf(c[mt][nt][3] + s1.y + b1r[nt][1], 0.f) * w2r[nt][1];
            }
        }
        #pragma unroll
        for (int mt = 0; mt < 2; mt++)
            #pragma unroll
            for (int hh = 0; hh < 2; hh++) {
                float p = pe[mt][hh];
                p += __shfl_xor_sync(0xFFFFFFFFu, p, 1);
                p += __shfl_xor_sync(0xFFFFFFFFu, p, 2);
                if (tig == 0) sP[(32 * wy + 16 * mt + 8 * hh + gid) * 4 + wx] = p;
            }
        __syncthreads();

        if (tid < 64) {
            int g = eBase + tid;
            if (g < E)
                out[g] = sP[tid * 4] + sP[tid * 4 + 1] + sP[tid * 4 + 2] + sP[tid * 4 + 3] + bias2;
        }
        __syncthreads();   // sP done; also orders next-tile buffer visibility
        cur ^= 1;
    }
}

extern "C" void kernel_launch(void* const* d_in, const int* in_sizes, int n_in,
                              void* d_out, int out_size) {
    const float* z    = (const float*)d_in[0];
    const int*   eidx = (const int*)d_in[1];   // int32 on the wire
    const float* W1   = (const float*)d_in[2];
    const float* b1   = (const float*)d_in[3];
    const float* W2   = (const float*)d_in[4];
    const float* b2   = (const float*)d_in[5];
    float*       out  = (float*)d_out;

    const int N = in_sizes[0] / DIM;           // 100000
    const int E = in_sizes[1] / 2;             // 500000
    const int t1 = (N + 63) / 64;              // 1563
    const int t2 = (E + 63) / 64;              // 7813

    __half* AB = nullptr; __half* ZH = nullptr;
    cudaGetSymbolAddress((void**)&AB, g_AB);
    cudaGetSymbolAddress((void**)&ZH, g_zh);

    const int k1_smem = 65536 + 16384;         // 81920
    cudaFuncSetAttribute(ab_gemm,  cudaFuncAttributeMaxDynamicSharedMemorySize, k1_smem);
    cudaFuncSetAttribute(edge_mlp, cudaFuncAttributeMaxDynamicSharedMemorySize, K2_SMEM);

    prep_w<<<192, 256>>>(W1);
    const int n2 = N * DIM / 2;
    prep_z<<<(n2 + 511) / 512, 512>>>(z, n2);
    ab_gemm<<<296, 256, k1_smem>>>(ZH, AB, N, t1);
    edge_mlp<<<296, 256, K2_SMEM>>>(ZH, eidx, b1, W2, b2, AB, out, E, t2);
}

// round 13
// speedup vs baseline: 5.0680x; 1.0102x over previous
#include <cuda_runtime.h>
#include <cuda_fp16.h>
#include <cstdint>

// MLPDecoder, split + fp16 mma.sync (m16n8k16, fp32 accum); persistent, 2 CTAs/SM.
// R13: hidden-dim permutation P so k1's AB stores are fully coalesced;
//      W1c/b1/W2 stored in P-order; b1 folded into S at gather time.
//  P(64wx+8nt+2tig+q) = (4wx+tig)*16 + 2nt + q   (applied to both 128-halves)
// edge_index is int32 on the wire (JAX x64 disabled).

#define DIM 128
#define NMAX 100000

__device__ __half g_Wab[256 * 128];           // [j][k] fp16 (orig col order)
__device__ __half g_Wc[128 * 128];            // [P(j)][k] fp16
__device__ __half g_b1h[128];                 // P-ordered fp16
__device__ float  g_w2p[128];                 // P-ordered fp32
__device__ __half g_AB[(size_t)NMAX * 256];   // fp16, P-ordered cols
__device__ __half g_zh[(size_t)NMAX * 128];   // fp16 copy of z

__device__ __forceinline__ int permJ(int j) {   // j in 0..127
    return (((j >> 6) * 4) + ((j >> 1) & 3)) * 16 + ((j >> 3) & 7) * 2 + (j & 1);
}

__device__ __forceinline__ void ldsm4(uint32_t& r0, uint32_t& r1, uint32_t& r2, uint32_t& r3,
                                      uint32_t addr) {
    asm volatile("ldmatrix.sync.aligned.m8n8.x4.shared.b16 {%0,%1,%2,%3}, [%4];"
                 : "=r"(r0), "=r"(r1), "=r"(r2), "=r"(r3) : "r"(addr));
}
__device__ __forceinline__ void mma_f16(
    float& c0, float& c1, float& c2, float& c3,
    uint32_t a0, uint32_t a1, uint32_t a2, uint32_t a3,
    uint32_t b0, uint32_t b1)
{
    asm volatile(
        "mma.sync.aligned.m16n8k16.row.col.f32.f16.f16.f32 "
        "{%0,%1,%2,%3}, {%4,%5,%6,%7}, {%8,%9}, {%0,%1,%2,%3};"
        : "+f"(c0), "+f"(c1), "+f"(c2), "+f"(c3)
        : "r"(a0), "r"(a1), "r"(a2), "r"(a3), "r"(b0), "r"(b1));
}

// ---------------------------------------------------------------------------
__global__ void prep_w(const float* __restrict__ W1, const float* __restrict__ b1,
                       const float* __restrict__ W2) {
    int i = blockIdx.x * 256 + threadIdx.x;
    if (i < 32768) {                       // Wab: [j 0..255][k], orig col order
        int j = i >> 7, k = i & 127;
        g_Wab[i] = __float2half_rn(W1[(k + (j < 128 ? 0 : 128)) * 128 + (j & 127)]);
    } else if (i < 49152) {                // Wc: row P(j)
        int l = i - 32768;
        int j = l >> 7, k = l & 127;
        g_Wc[permJ(j) * 128 + k] = __float2half_rn(W1[(256 + k) * 128 + j]);
    } else if (i < 49280) {
        int j = i - 49152;
        g_b1h[permJ(j)] = __float2half_rn(b1[j]);
    } else if (i < 49408) {
        int j = i - 49280;
        g_w2p[permJ(j)] = W2[j];
    }
}

__global__ void prep_z(const float* __restrict__ z, int n2) {
    int i = blockIdx.x * 512 + threadIdx.x;
    if (i < n2) {
        float2 a = ((const float2*)z)[i];
        ((half2*)g_zh)[i] = __floats2half2_rn(a.x, a.y);
    }
}

// ---------------------------------------------------------------------------
// Kernel 1: AB = z @ [W1a|W1b], cols written in P-order (coalesced STG.128).
// 64r x 256c tiles, K=128, 256 threads, 2 CTAs/SM.
// ---------------------------------------------------------------------------
__global__ __launch_bounds__(256, 2) void ab_gemm(
    const __half* __restrict__ zh, __half* __restrict__ AB, int N, int ntiles)
{
    extern __shared__ __align__(16) unsigned char smem[];
    const int tid  = threadIdx.x;
    const int warp = tid >> 5;
    const int lane = tid & 31;
    const int wy = warp >> 2, wx = warp & 3;
    const int gid = lane >> 2, tig = lane & 3;
    const int l7 = lane & 7;

    #pragma unroll
    for (int p = 0; p < 16; p++) {
        int i = p * 256 + tid;
        int j = i >> 4, uu = i & 15;
        uint4 w = __ldg((const uint4*)g_Wab + (size_t)j * 16 + uu);
        *(uint4*)(smem + j * 256 + ((uu ^ (j & 7)) << 4)) = w;
    }

    const uint32_t sWb = (uint32_t)__cvta_generic_to_shared(smem);
    const uint32_t sZb = sWb + 65536;
    const int rA = lane & 15;
    const int cA = lane >> 4;
    const int rBoff = ((lane >> 4) & 1) * 8 + l7;
    const int cB = (lane >> 3) & 1;

    const int r_s = tid & 63;
    const int q4  = tid >> 6;
    const int e7  = r_s & 7;
    const int jb  = (wx * 4 + tig) * 16;    // P-layout half offset for this thread
    __syncthreads();

    for (int tile = blockIdx.x; tile < ntiles; tile += gridDim.x) {
        const int rowBase = tile * 64;
        int zr = rowBase + r_s; if (zr >= N) zr = N - 1;
        const __half* zrow = zh + (size_t)zr * 128;

        auto ld1 = [&](int c) -> uint4 {
            return __ldg((const uint4*)(zrow + c * 32 + q4 * 8));
        };
        auto st1 = [&](int c, uint4 Z) {
            *(uint4*)(smem + 65536 + (c & 1) * 8192 + r_s * 128 + ((q4 ^ e7) << 4)) = Z;
        };

        st1(0, ld1(0));
        __syncthreads();

        float c[2][8][4];
        #pragma unroll
        for (int m = 0; m < 2; m++)
            #pragma unroll
            for (int n = 0; n < 8; n++)
                #pragma unroll
                for (int q = 0; q < 4; q++) c[m][n][q] = 0.f;

        #pragma unroll
        for (int ch = 0; ch < 4; ch++) {
            uint4 P;
            if (ch < 3) P = ld1(ch + 1);

            const uint32_t zbuf = sZb + (ch & 1) * 8192;
            #pragma unroll
            for (int ks = 0; ks < 2; ks++) {
                const int kk = ch * 2 + ks;
                uint32_t a[2][4];
                #pragma unroll
                for (int mt = 0; mt < 2; mt++)
                    ldsm4(a[mt][0], a[mt][1], a[mt][2], a[mt][3],
                          zbuf + (uint32_t)(32 * wy + 16 * mt + rA) * 128
                               + (uint32_t)(((ks * 2 + cA) ^ l7) << 4));
                #pragma unroll
                for (int g = 0; g < 4; g++) {
                    uint32_t b[4];
                    ldsm4(b[0], b[1], b[2], b[3],
                          sWb + (uint32_t)(64 * wx + 16 * g + rBoff) * 256
                              + (uint32_t)(((kk * 2 + cB) ^ l7) << 4));
                    #pragma unroll
                    for (int mt = 0; mt < 2; mt++) {
                        mma_f16(c[mt][2*g  ][0], c[mt][2*g  ][1], c[mt][2*g  ][2], c[mt][2*g  ][3],
                                a[mt][0], a[mt][1], a[mt][2], a[mt][3], b[0], b[1]);
                        mma_f16(c[mt][2*g+1][0], c[mt][2*g+1][1], c[mt][2*g+1][2], c[mt][2*g+1][3],
                                a[mt][0], a[mt][1], a[mt][2], a[mt][3], b[2], b[3]);
                    }
                }
            }
            if (ch < 3) st1(ch + 1, P);
            __syncthreads();
        }

        // P-ordered coalesced store: thread owns 16 contiguous halves per row
        #pragma unroll
        for (int mt = 0; mt < 2; mt++) {
            int r0 = rowBase + 32 * wy + 16 * mt + gid;
            int r1 = r0 + 8;
            uint4 o0, o1, p0, p1;
            half2* oa = (half2*)&o0; half2* ob = (half2*)&o1;
            half2* pa = (half2*)&p0; half2* pb = (half2*)&p1;
            #pragma unroll
            for (int nt = 0; nt < 4; nt++) {
                oa[nt] = __floats2half2_rn(c[mt][nt][0],     c[mt][nt][1]);
                ob[nt] = __floats2half2_rn(c[mt][nt + 4][0], c[mt][nt + 4][1]);
                pa[nt] = __floats2half2_rn(c[mt][nt][2],     c[mt][nt][3]);
                pb[nt] = __floats2half2_rn(c[mt][nt + 4][2], c[mt][nt + 4][3]);
            }
            if (r0 < N) {
                *(uint4*)(AB + (size_t)r0 * 256 + jb)     = o0;
                *(uint4*)(AB + (size_t)r0 * 256 + jb + 8) = o1;
            }
            if (r1 < N) {
                *(uint4*)(AB + (size_t)r1 * 256 + jb)     = p0;
                *(uint4*)(AB + (size_t)r1 * 256 + jb + 8) = p1;
            }
        }
        __syncthreads();
    }
}

// ---------------------------------------------------------------------------
// Kernel 2: 64-edge tiles; coalesced gathers; cross-tile double buffering.
// S = ABu + ABv + b1 folded at stage time (all P-ordered).
// smem: sW 32768 + sF 2x16384 + sS16 2x17408 + sP 1024 = 101376 -> 2 CTAs/SM.
// ---------------------------------------------------------------------------
#define K2_SF   32768
#define K2_SS   65536
#define K2_SP   100352
#define K2_SMEM 101376

struct G4 { uint4 U, V, A, B; };

__global__ __launch_bounds__(256, 2) void edge_mlp(
    const __half* __restrict__ zh, const int* __restrict__ eidx,
    const float* __restrict__ b2, const __half* __restrict__ AB,
    float* __restrict__ out, int E, int ntiles)
{
    extern __shared__ __align__(16) unsigned char smem[];
    float* sP = (float*)(smem + K2_SP);

    const int tid  = threadIdx.x;
    const int warp = tid >> 5;
    const int lane = tid & 31;
    const int wy = warp >> 2, wx = warp & 3;
    const int gid = lane >> 2, tig = lane & 3;
    const int l7 = lane & 7;

    // stage W1c (P-ordered rows) once
    #pragma unroll
    for (int p = 0; p < 8; p++) {
        int i = p * 256 + tid;
        int j = i >> 4, uu = i & 15;
        uint4 w = __ldg((const uint4*)g_Wc + (size_t)j * 16 + uu);
        *(uint4*)(smem + j * 256 + ((uu ^ (j & 7)) << 4)) = w;
    }

    const uint32_t sWb = (uint32_t)__cvta_generic_to_shared(smem);
    const uint32_t sFb = sWb + K2_SF;
    const int rA = lane & 15;
    const int cA = lane >> 4;
    const int rBoff = ((lane >> 4) & 1) * 8 + l7;
    const int cB = (lane >> 3) & 1;

    const int eh  = lane >> 4;          // 0/1: which of the warp's 2 edges
    const int u16 = lane & 15;          // 16B unit within 256B row
    const float bias2 = __ldg(b2);

    // hoisted: this thread's 8 b1 halves (P-ordered) and 8 w2 floats
    const uint4 B1 = *(const uint4*)(g_b1h + u16 * 8);
    float w2r[4][2];
    #pragma unroll
    for (int nt = 0; nt < 4; nt++) {
        int j = 32 * wx + 8 * nt + 2 * tig;
        w2r[nt][0] = __ldg(g_w2p + j); w2r[nt][1] = __ldg(g_w2p + j + 1);
    }
    __syncthreads();

    auto ld_pass = [&](int p, int base, G4& g) {
        int e_loc = p * 16 + warp * 2 + eh;
        int ge = base + e_loc;
        int u = 0, v = 0;
        if (ge < E) { u = eidx[ge]; v = eidx[E + ge]; }
        g.U = __ldg((const uint4*)(zh + (size_t)u * 128) + u16);
        g.V = __ldg((const uint4*)(zh + (size_t)v * 128) + u16);
        g.A = __ldg((const uint4*)(AB + (size_t)u * 256) + u16);
        g.B = __ldg((const uint4*)(AB + (size_t)v * 256 + 128) + u16);
    };
    auto st_pass = [&](int p, const G4& g, int nb) {
        int e_loc = p * 16 + warp * 2 + eh;
        const half2* up = (const half2*)&g.U;
        const half2* vp = (const half2*)&g.V;
        uint4 D; half2* dp = (half2*)&D;
        #pragma unroll
        for (int i = 0; i < 4; i++) dp[i] = __habs2(__hsub2(up[i], vp[i]));
        *(uint4*)(smem + K2_SF + nb * 16384 + e_loc * 256 + ((u16 ^ (e_loc & 7)) << 4)) = D;
        const half2* ap = (const half2*)&g.A;
        const half2* bp = (const half2*)&g.B;
        const half2* b1p = (const half2*)&B1;
        uint4 S; half2* sp = (half2*)&S;
        #pragma unroll
        for (int i = 0; i < 4; i++) sp[i] = __hadd2(__hadd2(ap[i], bp[i]), b1p[i]);
        *(uint4*)(smem + K2_SS + nb * 17408 + e_loc * 272 + u16 * 16) = S;
    };

    int tile = blockIdx.x;
    if (tile < ntiles) {
        #pragma unroll
        for (int p = 0; p < 4; p++) { G4 g; ld_pass(p, tile * 64, g); st_pass(p, g, 0); }
    }
    __syncthreads();

    int cur = 0;
    for (; tile < ntiles; tile += gridDim.x) {
        const int eBase = tile * 64;
        const int nxt = tile + gridDim.x;
        const bool hasNext = nxt < ntiles;
        const uint32_t fbuf = sFb + cur * 16384;
        const __half* sS16 = (const __half*)(smem + K2_SS + cur * 17408);

        float c[2][4][4];
        #pragma unroll
        for (int m = 0; m < 2; m++)
            #pragma unroll
            for (int n = 0; n < 4; n++)
                #pragma unroll
                for (int q = 0; q < 4; q++) c[m][n][q] = 0.f;

        #pragma unroll
        for (int p = 0; p < 4; p++) {
            G4 g;
            if (hasNext) ld_pass(p, nxt * 64, g);
            #pragma unroll
            for (int ks2 = 0; ks2 < 2; ks2++) {
                const int kk = p * 2 + ks2;
                uint32_t a[2][4];
                #pragma unroll
                for (int mt = 0; mt < 2; mt++)
                    ldsm4(a[mt][0], a[mt][1], a[mt][2], a[mt][3],
                          fbuf + (uint32_t)(32 * wy + 16 * mt + rA) * 256
                               + (uint32_t)(((kk * 2 + cA) ^ l7) << 4));
                #pragma unroll
                for (int g2 = 0; g2 < 2; g2++) {
                    uint32_t b[4];
                    ldsm4(b[0], b[1], b[2], b[3],
                          sWb + (uint32_t)(32 * wx + 16 * g2 + rBoff) * 256
                              + (uint32_t)(((kk * 2 + cB) ^ l7) << 4));
                    #pragma unroll
                    for (int mt = 0; mt < 2; mt++) {
                        mma_f16(c[mt][2*g2  ][0], c[mt][2*g2  ][1], c[mt][2*g2  ][2], c[mt][2*g2  ][3],
                                a[mt][0], a[mt][1], a[mt][2], a[mt][3], b[0], b[1]);
                        mma_f16(c[mt][2*g2+1][0], c[mt][2*g2+1][1], c[mt][2*g2+1][2], c[mt][2*g2+1][3],
                                a[mt][0], a[mt][1], a[mt][2], a[mt][3], b[2], b[3]);
                    }
                }
            }
            if (hasNext) st_pass(p, g, cur ^ 1);
        }

        // epilogue: h = relu(C + S); partial = h . W2   (b1 already in S)
        float pe[2][2] = {{0.f, 0.f}, {0.f, 0.f}};
        #pragma unroll
        for (int mt = 0; mt < 2; mt++) {
            int e0 = 32 * wy + 16 * mt + gid;
            #pragma unroll
            for (int nt = 0; nt < 4; nt++) {
                int j = 32 * wx + 8 * nt + 2 * tig;
                float2 s0 = __half22float2(*(const half2*)(sS16 + e0 * 136 + j));
                float2 s1 = __half22float2(*(const half2*)(sS16 + (e0 + 8) * 136 + j));
                pe[mt][0] += fmaxf(c[mt][nt][0] + s0.x, 0.f) * w2r[nt][0]
                           + fmaxf(c[mt][nt][1] + s0.y, 0.f) * w2r[nt][1];
                pe[mt][1] += fmaxf(c[mt][nt][2] + s1.x, 0.f) * w2r[nt][0]
                           + fmaxf(c[mt][nt][3] + s1.y, 0.f) * w2r[nt][1];
            }
        }
        #pragma unroll
        for (int mt = 0; mt < 2; mt++)
            #pragma unroll
            for (int hh = 0; hh < 2; hh++) {
                float p = pe[mt][hh];
                p += __shfl_xor_sync(0xFFFFFFFFu, p, 1);
                p += __shfl_xor_sync(0xFFFFFFFFu, p, 2);
                if (tig == 0) sP[(32 * wy + 16 * mt + 8 * hh + gid) * 4 + wx] = p;
            }
        __syncthreads();

        if (tid < 64) {
            int g = eBase + tid;
            if (g < E)
                out[g] = sP[tid * 4] + sP[tid * 4 + 1] + sP[tid * 4 + 2] + sP[tid * 4 + 3] + bias2;
        }
        __syncthreads();
        cur ^= 1;
    }
}

extern "C" void kernel_launch(void* const* d_in, const int* in_sizes, int n_in,
                              void* d_out, int out_size) {
    const float* z    = (const float*)d_in[0];
    const int*   eidx = (const int*)d_in[1];   // int32 on the wire
    const float* W1   = (const float*)d_in[2];
    const float* b1   = (const float*)d_in[3];
    const float* W2   = (const float*)d_in[4];
    const float* b2   = (const float*)d_in[5];
    float*       out  = (float*)d_out;

    const int N = in_sizes[0] / DIM;           // 100000
    const int E = in_sizes[1] / 2;             // 500000
    const int t1 = (N + 63) / 64;              // 1563
    const int t2 = (E + 63) / 64;              // 7813

    __half* AB = nullptr; __half* ZH = nullptr;
    cudaGetSymbolAddress((void**)&AB, g_AB);
    cudaGetSymbolAddress((void**)&ZH, g_zh);

    const int k1_smem = 65536 + 16384;         // 81920
    cudaFuncSetAttribute(ab_gemm,  cudaFuncAttributeMaxDynamicSharedMemorySize, k1_smem);
    cudaFuncSetAttribute(edge_mlp, cudaFuncAttributeMaxDynamicSharedMemorySize, K2_SMEM);

    prep_w<<<194, 256>>>(W1, b1, W2);
    const int n2 = N * DIM / 2;
    prep_z<<<(n2 + 511) / 512, 512>>>(z, n2);
    ab_gemm<<<296, 256, k1_smem>>>(ZH, AB, N, t1);
    edge_mlp<<<296, 256, K2_SMEM>>>(ZH, eidx, b2, AB, out, E, t2);
}

// round 14
// speedup vs baseline: 5.2756x; 1.0410x over previous
#include <cuda_runtime.h>
#include <cuda_fp16.h>
#include <cstdint>

// MLPDecoder, split + fp16 mma.sync (m16n8k16, fp32 accum); persistent, 2 CTAs/SM.
// R14: prep_z fused into ab_gemm (reads z fp32, emits g_zh + AB); single prep kernel.
//  P(j) hidden-dim permutation as in R13 (coalesced AB stores; W1c/b1/W2 P-ordered).
// edge_index is int32 on the wire (JAX x64 disabled).

#define DIM 128
#define NMAX 100000

__device__ __half g_Wab[256 * 128];           // [j][k] fp16 (orig col order)
__device__ __half g_Wc[128 * 128];            // [P(j)][k] fp16
__device__ __half g_b1h[128];                 // P-ordered fp16
__device__ float  g_w2p[128];                 // P-ordered fp32
__device__ __half g_AB[(size_t)NMAX * 256];   // fp16, P-ordered cols
__device__ __half g_zh[(size_t)NMAX * 128];   // fp16 copy of z (written by ab_gemm)

__device__ __forceinline__ int permJ(int j) {
    return (((j >> 6) * 4) + ((j >> 1) & 3)) * 16 + ((j >> 3) & 7) * 2 + (j & 1);
}

__device__ __forceinline__ void ldsm4(uint32_t& r0, uint32_t& r1, uint32_t& r2, uint32_t& r3,
                                      uint32_t addr) {
    asm volatile("ldmatrix.sync.aligned.m8n8.x4.shared.b16 {%0,%1,%2,%3}, [%4];"
                 : "=r"(r0), "=r"(r1), "=r"(r2), "=r"(r3) : "r"(addr));
}
__device__ __forceinline__ void mma_f16(
    float& c0, float& c1, float& c2, float& c3,
    uint32_t a0, uint32_t a1, uint32_t a2, uint32_t a3,
    uint32_t b0, uint32_t b1)
{
    asm volatile(
        "mma.sync.aligned.m16n8k16.row.col.f32.f16.f16.f32 "
        "{%0,%1,%2,%3}, {%4,%5,%6,%7}, {%8,%9}, {%0,%1,%2,%3};"
        : "+f"(c0), "+f"(c1), "+f"(c2), "+f"(c3)
        : "r"(a0), "r"(a1), "r"(a2), "r"(a3), "r"(b0), "r"(b1));
}

// ---------------------------------------------------------------------------
__global__ void prep_w(const float* __restrict__ W1, const float* __restrict__ b1,
                       const float* __restrict__ W2) {
    int i = blockIdx.x * 256 + threadIdx.x;
    if (i < 32768) {                       // Wab: [j 0..255][k], orig col order
        int j = i >> 7, k = i & 127;
        g_Wab[i] = __float2half_rn(W1[(k + (j < 128 ? 0 : 128)) * 128 + (j & 127)]);
    } else if (i < 49152) {                // Wc: row P(j)
        int l = i - 32768;
        int j = l >> 7, k = l & 127;
        g_Wc[permJ(j) * 128 + k] = __float2half_rn(W1[(256 + k) * 128 + j]);
    } else if (i < 49280) {
        int j = i - 49152;
        g_b1h[permJ(j)] = __float2half_rn(b1[j]);
    } else if (i < 49408) {
        int j = i - 49280;
        g_w2p[permJ(j)] = W2[j];
    }
}

// ---------------------------------------------------------------------------
// Kernel 1: AB = z @ [W1a|W1b] (P-ordered coalesced stores) + emit zh = fp16(z).
// Reads z fp32 directly. 64r x 256c tiles, K=128, 256 threads, 2 CTAs/SM.
// ---------------------------------------------------------------------------
__global__ __launch_bounds__(256, 2) void ab_gemm(
    const float* __restrict__ z, __half* __restrict__ AB,
    __half* __restrict__ zh, int N, int ntiles)
{
    extern __shared__ __align__(16) unsigned char smem[];
    const int tid  = threadIdx.x;
    const int warp = tid >> 5;
    const int lane = tid & 31;
    const int wy = warp >> 2, wx = warp & 3;
    const int gid = lane >> 2, tig = lane & 3;
    const int l7 = lane & 7;

    #pragma unroll
    for (int p = 0; p < 16; p++) {
        int i = p * 256 + tid;
        int j = i >> 4, uu = i & 15;
        uint4 w = __ldg((const uint4*)g_Wab + (size_t)j * 16 + uu);
        *(uint4*)(smem + j * 256 + ((uu ^ (j & 7)) << 4)) = w;
    }

    const uint32_t sWb = (uint32_t)__cvta_generic_to_shared(smem);
    const uint32_t sZb = sWb + 65536;
    const int rA = lane & 15;
    const int cA = lane >> 4;
    const int rBoff = ((lane >> 4) & 1) * 8 + l7;
    const int cB = (lane >> 3) & 1;

    const int r_s = tid & 63;
    const int q4  = tid >> 6;
    const int e7  = r_s & 7;
    const int jb  = (wx * 4 + tig) * 16;
    __syncthreads();

    for (int tile = blockIdx.x; tile < ntiles; tile += gridDim.x) {
        const int rowBase = tile * 64;
        int zr = rowBase + r_s; if (zr >= N) zr = N - 1;
        const float* zrow = z + (size_t)zr * 128;
        __half* zhrow = zh + (size_t)zr * 128;

        auto ld1 = [&](int c, float4& A0, float4& A1) {
            const float4* src = (const float4*)(zrow + c * 32 + q4 * 8);
            A0 = __ldg(src); A1 = __ldg(src + 1);
        };
        auto st1 = [&](int c, float4 A0, float4 A1) {
            uint4 Z; half2* zp = (half2*)&Z;
            zp[0] = __floats2half2_rn(A0.x, A0.y);
            zp[1] = __floats2half2_rn(A0.z, A0.w);
            zp[2] = __floats2half2_rn(A1.x, A1.y);
            zp[3] = __floats2half2_rn(A1.z, A1.w);
            *(uint4*)(smem + 65536 + (c & 1) * 8192 + r_s * 128 + ((q4 ^ e7) << 4)) = Z;
            *(uint4*)(zhrow + c * 32 + q4 * 8) = Z;     // side output for k2
        };

        { float4 A0, A1; ld1(0, A0, A1); st1(0, A0, A1); }
        __syncthreads();

        float c[2][8][4];
        #pragma unroll
        for (int m = 0; m < 2; m++)
            #pragma unroll
            for (int n = 0; n < 8; n++)
                #pragma unroll
                for (int q = 0; q < 4; q++) c[m][n][q] = 0.f;

        #pragma unroll
        for (int ch = 0; ch < 4; ch++) {
            float4 P0, P1;
            if (ch < 3) ld1(ch + 1, P0, P1);

            const uint32_t zbuf = sZb + (ch & 1) * 8192;
            #pragma unroll
            for (int ks = 0; ks < 2; ks++) {
                const int kk = ch * 2 + ks;
                uint32_t a[2][4];
                #pragma unroll
                for (int mt = 0; mt < 2; mt++)
                    ldsm4(a[mt][0], a[mt][1], a[mt][2], a[mt][3],
                          zbuf + (uint32_t)(32 * wy + 16 * mt + rA) * 128
                               + (uint32_t)(((ks * 2 + cA) ^ l7) << 4));
                #pragma unroll
                for (int g = 0; g < 4; g++) {
                    uint32_t b[4];
                    ldsm4(b[0], b[1], b[2], b[3],
                          sWb + (uint32_t)(64 * wx + 16 * g + rBoff) * 256
                              + (uint32_t)(((kk * 2 + cB) ^ l7) << 4));
                    #pragma unroll
                    for (int mt = 0; mt < 2; mt++) {
                        mma_f16(c[mt][2*g  ][0], c[mt][2*g  ][1], c[mt][2*g  ][2], c[mt][2*g  ][3],
                                a[mt][0], a[mt][1], a[mt][2], a[mt][3], b[0], b[1]);
                        mma_f16(c[mt][2*g+1][0], c[mt][2*g+1][1], c[mt][2*g+1][2], c[mt][2*g+1][3],
                                a[mt][0], a[mt][1], a[mt][2], a[mt][3], b[2], b[3]);
                    }
                }
            }
            if (ch < 3) st1(ch + 1, P0, P1);
            __syncthreads();
        }

        #pragma unroll
        for (int mt = 0; mt < 2; mt++) {
            int r0 = rowBase + 32 * wy + 16 * mt + gid;
            int r1 = r0 + 8;
            uint4 o0, o1, p0, p1;
            half2* oa = (half2*)&o0; half2* ob = (half2*)&o1;
            half2* pa = (half2*)&p0; half2* pb = (half2*)&p1;
            #pragma unroll
            for (int nt = 0; nt < 4; nt++) {
                oa[nt] = __floats2half2_rn(c[mt][nt][0],     c[mt][nt][1]);
                ob[nt] = __floats2half2_rn(c[mt][nt + 4][0], c[mt][nt + 4][1]);
                pa[nt] = __floats2half2_rn(c[mt][nt][2],     c[mt][nt][3]);
                pb[nt] = __floats2half2_rn(c[mt][nt + 4][2], c[mt][nt + 4][3]);
            }
            if (r0 < N) {
                *(uint4*)(AB + (size_t)r0 * 256 + jb)     = o0;
                *(uint4*)(AB + (size_t)r0 * 256 + jb + 8) = o1;
            }
            if (r1 < N) {
                *(uint4*)(AB + (size_t)r1 * 256 + jb)     = p0;
                *(uint4*)(AB + (size_t)r1 * 256 + jb + 8) = p1;
            }
        }
        __syncthreads();
    }
}

// ---------------------------------------------------------------------------
// Kernel 2 (unchanged from R13): 64-edge tiles; coalesced gathers;
// cross-tile double buffering; b1 folded into S.
// ---------------------------------------------------------------------------
#define K2_SF   32768
#define K2_SS   65536
#define K2_SP   100352
#define K2_SMEM 101376

struct G4 { uint4 U, V, A, B; };

__global__ __launch_bounds__(256, 2) void edge_mlp(
    const __half* __restrict__ zh, const int* __restrict__ eidx,
    const float* __restrict__ b2, const __half* __restrict__ AB,
    float* __restrict__ out, int E, int ntiles)
{
    extern __shared__ __align__(16) unsigned char smem[];
    float* sP = (float*)(smem + K2_SP);

    const int tid  = threadIdx.x;
    const int warp = tid >> 5;
    const int lane = tid & 31;
    const int wy = warp >> 2, wx = warp & 3;
    const int gid = lane >> 2, tig = lane & 3;
    const int l7 = lane & 7;

    #pragma unroll
    for (int p = 0; p < 8; p++) {
        int i = p * 256 + tid;
        int j = i >> 4, uu = i & 15;
        uint4 w = __ldg((const uint4*)g_Wc + (size_t)j * 16 + uu);
        *(uint4*)(smem + j * 256 + ((uu ^ (j & 7)) << 4)) = w;
    }

    const uint32_t sWb = (uint32_t)__cvta_generic_to_shared(smem);
    const uint32_t sFb = sWb + K2_SF;
    const int rA = lane & 15;
    const int cA = lane >> 4;
    const int rBoff = ((lane >> 4) & 1) * 8 + l7;
    const int cB = (lane >> 3) & 1;

    const int eh  = lane >> 4;
    const int u16 = lane & 15;
    const float bias2 = __ldg(b2);

    const uint4 B1 = *(const uint4*)(g_b1h + u16 * 8);
    float w2r[4][2];
    #pragma unroll
    for (int nt = 0; nt < 4; nt++) {
        int j = 32 * wx + 8 * nt + 2 * tig;
        w2r[nt][0] = __ldg(g_w2p + j); w2r[nt][1] = __ldg(g_w2p + j + 1);
    }
    __syncthreads();

    auto ld_pass = [&](int p, int base, G4& g) {
        int e_loc = p * 16 + warp * 2 + eh;
        int ge = base + e_loc;
        int u = 0, v = 0;
        if (ge < E) { u = eidx[ge]; v = eidx[E + ge]; }
        g.U = __ldg((const uint4*)(zh + (size_t)u * 128) + u16);
        g.V = __ldg((const uint4*)(zh + (size_t)v * 128) + u16);
        g.A = __ldg((const uint4*)(AB + (size_t)u * 256) + u16);
        g.B = __ldg((const uint4*)(AB + (size_t)v * 256 + 128) + u16);
    };
    auto st_pass = [&](int p, const G4& g, int nb) {
        int e_loc = p * 16 + warp * 2 + eh;
        const half2* up = (const half2*)&g.U;
        const half2* vp = (const half2*)&g.V;
        uint4 D; half2* dp = (half2*)&D;
        #pragma unroll
        for (int i = 0; i < 4; i++) dp[i] = __habs2(__hsub2(up[i], vp[i]));
        *(uint4*)(smem + K2_SF + nb * 16384 + e_loc * 256 + ((u16 ^ (e_loc & 7)) << 4)) = D;
        const half2* ap = (const half2*)&g.A;
        const half2* bp = (const half2*)&g.B;
        const half2* b1p = (const half2*)&B1;
        uint4 S; half2* sp = (half2*)&S;
        #pragma unroll
        for (int i = 0; i < 4; i++) sp[i] = __hadd2(__hadd2(ap[i], bp[i]), b1p[i]);
        *(uint4*)(smem + K2_SS + nb * 17408 + e_loc * 272 + u16 * 16) = S;
    };

    int tile = blockIdx.x;
    if (tile < ntiles) {
        #pragma unroll
        for (int p = 0; p < 4; p++) { G4 g; ld_pass(p, tile * 64, g); st_pass(p, g, 0); }
    }
    __syncthreads();

    int cur = 0;
    for (; tile < ntiles; tile += gridDim.x) {
        const int eBase = tile * 64;
        const int nxt = tile + gridDim.x;
        const bool hasNext = nxt < ntiles;
        const uint32_t fbuf = sFb + cur * 16384;
        const __half* sS16 = (const __half*)(smem + K2_SS + cur * 17408);

        float c[2][4][4];
        #pragma unroll
        for (int m = 0; m < 2; m++)
            #pragma unroll
            for (int n = 0; n < 4; n++)
                #pragma unroll
                for (int q = 0; q < 4; q++) c[m][n][q] = 0.f;

        #pragma unroll
        for (int p = 0; p < 4; p++) {
            G4 g;
            if (hasNext) ld_pass(p, nxt * 64, g);
            #pragma unroll
            for (int ks2 = 0; ks2 < 2; ks2++) {
                const int kk = p * 2 + ks2;
                uint32_t a[2][4];
                #pragma unroll
                for (int mt = 0; mt < 2; mt++)
                    ldsm4(a[mt][0], a[mt][1], a[mt][2], a[mt][3],
                          fbuf + (uint32_t)(32 * wy + 16 * mt + rA) * 256
                               + (uint32_t)(((kk * 2 + cA) ^ l7) << 4));
                #pragma unroll
                for (int g2 = 0; g2 < 2; g2++) {
                    uint32_t b[4];
                    ldsm4(b[0], b[1], b[2], b[3],
                          sWb + (uint32_t)(32 * wx + 16 * g2 + rBoff) * 256
                              + (uint32_t)(((kk * 2 + cB) ^ l7) << 4));
                    #pragma unroll
                    for (int mt = 0; mt < 2; mt++) {
                        mma_f16(c[mt][2*g2  ][0], c[mt][2*g2  ][1], c[mt][2*g2  ][2], c[mt][2*g2  ][3],
                                a[mt][0], a[mt][1], a[mt][2], a[mt][3], b[0], b[1]);
                        mma_f16(c[mt][2*g2+1][0], c[mt][2*g2+1][1], c[mt][2*g2+1][2], c[mt][2*g2+1][3],
                                a[mt][0], a[mt][1], a[mt][2], a[mt][3], b[2], b[3]);
                    }
                }
            }
            if (hasNext) st_pass(p, g, cur ^ 1);
        }

        float pe[2][2] = {{0.f, 0.f}, {0.f, 0.f}};
        #pragma unroll
        for (int mt = 0; mt < 2; mt++) {
            int e0 = 32 * wy + 16 * mt + gid;
            #pragma unroll
            for (int nt = 0; nt < 4; nt++) {
                int j = 32 * wx + 8 * nt + 2 * tig;
                float2 s0 = __half22float2(*(const half2*)(sS16 + e0 * 136 + j));
                float2 s1 = __half22float2(*(const half2*)(sS16 + (e0 + 8) * 136 + j));
                pe[mt][0] += fmaxf(c[mt][nt][0] + s0.x, 0.f) * w2r[nt][0]
                           + fmaxf(c[mt][nt][1] + s0.y, 0.f) * w2r[nt][1];
                pe[mt][1] += fmaxf(c[mt][nt][2] + s1.x, 0.f) * w2r[nt][0]
                           + fmaxf(c[mt][nt][3] + s1.y, 0.f) * w2r[nt][1];
            }
        }
        #pragma unroll
        for (int mt = 0; mt < 2; mt++)
            #pragma unroll
            for (int hh = 0; hh < 2; hh++) {
                float p = pe[mt][hh];
                p += __shfl_xor_sync(0xFFFFFFFFu, p, 1);
                p += __shfl_xor_sync(0xFFFFFFFFu, p, 2);
                if (tig == 0) sP[(32 * wy + 16 * mt + 8 * hh + gid) * 4 + wx] = p;
            }
        __syncthreads();

        if (tid < 64) {
            int g = eBase + tid;
            if (g < E)
                out[g] = sP[tid * 4] + sP[tid * 4 + 1] + sP[tid * 4 + 2] + sP[tid * 4 + 3] + bias2;
        }
        __syncthreads();
        cur ^= 1;
    }
}

extern "C" void kernel_launch(void* const* d_in, const int* in_sizes, int n_in,
                              void* d_out, int out_size) {
    const float* z    = (const float*)d_in[0];
    const int*   eidx = (const int*)d_in[1];   // int32 on the wire
    const float* W1   = (const float*)d_in[2];
    const float* b1   = (const float*)d_in[3];
    const float* W2   = (const float*)d_in[4];
    const float* b2   = (const float*)d_in[5];
    float*       out  = (float*)d_out;

    const int N = in_sizes[0] / DIM;           // 100000
    const int E = in_sizes[1] / 2;             // 500000
    const int t1 = (N + 63) / 64;              // 1563
    const int t2 = (E + 63) / 64;              // 7813

    __half* AB = nullptr; __half* ZH = nullptr;
    cudaGetSymbolAddress((void**)&AB, g_AB);
    cudaGetSymbolAddress((void**)&ZH, g_zh);

    const int k1_smem = 65536 + 16384;         // 81920
    cudaFuncSetAttribute(ab_gemm,  cudaFuncAttributeMaxDynamicSharedMemorySize, k1_smem);
    cudaFuncSetAttribute(edge_mlp, cudaFuncAttributeMaxDynamicSharedMemorySize, K2_SMEM);

    prep_w<<<194, 256>>>(W1, b1, W2);
    ab_gemm<<<296, 256, k1_smem>>>(z, AB, ZH, N, t1);
    edge_mlp<<<296, 256, K2_SMEM>>>(ZH, eidx, b2, AB, out, E, t2);
}

// round 15
// speedup vs baseline: 5.7650x; 1.0928x over previous
#include <cuda_runtime.h>
#include <cuda_fp16.h>
#include <cstdint>

// MLPDecoder, split + fp16 mma.sync (m16n8k16, fp32 accum); persistent, 2 CTAs/SM.
// R15: k1 restructured to k2-style cross-tile double buffering (1 sync/tile,
//      next-tile z loads hidden under current-tile MMA). k2 unchanged.
//  P(j) hidden-dim permutation as in R13. edge_index is int32 on the wire.

#define DIM 128
#define NMAX 100000

__device__ __half g_Wab[256 * 128];           // [j][k] fp16 (orig col order)
__device__ __half g_Wc[128 * 128];            // [P(j)][k] fp16
__device__ __half g_b1h[128];                 // P-ordered fp16
__device__ float  g_w2p[128];                 // P-ordered fp32
__device__ __half g_AB[(size_t)NMAX * 256];   // fp16, P-ordered cols
__device__ __half g_zh[(size_t)NMAX * 128];   // fp16 copy of z (written by ab_gemm)

__device__ __forceinline__ int permJ(int j) {
    return (((j >> 6) * 4) + ((j >> 1) & 3)) * 16 + ((j >> 3) & 7) * 2 + (j & 1);
}

__device__ __forceinline__ void ldsm4(uint32_t& r0, uint32_t& r1, uint32_t& r2, uint32_t& r3,
                                      uint32_t addr) {
    asm volatile("ldmatrix.sync.aligned.m8n8.x4.shared.b16 {%0,%1,%2,%3}, [%4];"
                 : "=r"(r0), "=r"(r1), "=r"(r2), "=r"(r3) : "r"(addr));
}
__device__ __forceinline__ void mma_f16(
    float& c0, float& c1, float& c2, float& c3,
    uint32_t a0, uint32_t a1, uint32_t a2, uint32_t a3,
    uint32_t b0, uint32_t b1)
{
    asm volatile(
        "mma.sync.aligned.m16n8k16.row.col.f32.f16.f16.f32 "
        "{%0,%1,%2,%3}, {%4,%5,%6,%7}, {%8,%9}, {%0,%1,%2,%3};"
        : "+f"(c0), "+f"(c1), "+f"(c2), "+f"(c3)
        : "r"(a0), "r"(a1), "r"(a2), "r"(a3), "r"(b0), "r"(b1));
}

// ---------------------------------------------------------------------------
__global__ void prep_w(const float* __restrict__ W1, const float* __restrict__ b1,
                       const float* __restrict__ W2) {
    int i = blockIdx.x * 256 + threadIdx.x;
    if (i < 32768) {                       // Wab: [j 0..255][k], orig col order
        int j = i >> 7, k = i & 127;
        g_Wab[i] = __float2half_rn(W1[(k + (j < 128 ? 0 : 128)) * 128 + (j & 127)]);
    } else if (i < 49152) {                // Wc: row P(j)
        int l = i - 32768;
        int j = l >> 7, k = l & 127;
        g_Wc[permJ(j) * 128 + k] = __float2half_rn(W1[(256 + k) * 128 + j]);
    } else if (i < 49280) {
        int j = i - 49152;
        g_b1h[permJ(j)] = __float2half_rn(b1[j]);
    } else if (i < 49408) {
        int j = i - 49280;
        g_w2p[permJ(j)] = W2[j];
    }
}

// ---------------------------------------------------------------------------
// Kernel 1 (R15): AB = z @ [W1a|W1b] (P-ordered coalesced stores) + zh = fp16(z).
// 64r x 256c tiles, K=128; cross-tile double-buffered z staging, 1 sync/tile.
// smem: sW [256j][256B] 65536 + sZ 2 x (64r x 256B) 32768 = 98304 -> 2 CTAs/SM.
// ---------------------------------------------------------------------------
__global__ __launch_bounds__(256, 2) void ab_gemm(
    const float* __restrict__ z, __half* __restrict__ AB,
    __half* __restrict__ zh, int N, int ntiles)
{
    extern __shared__ __align__(16) unsigned char smem[];
    const int tid  = threadIdx.x;
    const int warp = tid >> 5;
    const int lane = tid & 31;
    const int wy = warp >> 2, wx = warp & 3;
    const int gid = lane >> 2, tig = lane & 3;
    const int l7 = lane & 7;

    // stage W once (rows 256B, XOR swizzled)
    #pragma unroll
    for (int p = 0; p < 16; p++) {
        int i = p * 256 + tid;
        int j = i >> 4, uu = i & 15;
        uint4 w = __ldg((const uint4*)g_Wab + (size_t)j * 16 + uu);
        *(uint4*)(smem + j * 256 + ((uu ^ (j & 7)) << 4)) = w;
    }

    const uint32_t sWb = (uint32_t)__cvta_generic_to_shared(smem);
    const uint32_t sZb = sWb + 65536;
    const int rA = lane & 15;
    const int cA = lane >> 4;
    const int rBoff = ((lane >> 4) & 1) * 8 + l7;
    const int cB = (lane >> 3) & 1;

    // staging mapping (mirror of k2): 16 lanes per row, u16 = 16B unit
    const int eh  = lane >> 4;          // 0/1: which of the warp's 2 rows
    const int u16 = lane & 15;          // 16B unit within 256B fp16 row
    const int jb  = (wx * 4 + tig) * 16;
    __syncthreads();

    auto ld_pass = [&](int p, int base, float4& A0, float4& A1) {
        int r_loc = p * 16 + warp * 2 + eh;
        int zr = base + r_loc; if (zr >= N) zr = N - 1;
        const float4* src = (const float4*)(z + (size_t)zr * 128) + u16 * 2;
        A0 = __ldg(src); A1 = __ldg(src + 1);
    };
    auto st_pass = [&](int p, int base, float4 A0, float4 A1, int nb) {
        int r_loc = p * 16 + warp * 2 + eh;
        uint4 Z; half2* zp = (half2*)&Z;
        zp[0] = __floats2half2_rn(A0.x, A0.y);
        zp[1] = __floats2half2_rn(A0.z, A0.w);
        zp[2] = __floats2half2_rn(A1.x, A1.y);
        zp[3] = __floats2half2_rn(A1.z, A1.w);
        *(uint4*)(smem + 65536 + nb * 16384 + r_loc * 256 + ((u16 ^ (r_loc & 7)) << 4)) = Z;
        int zr = base + r_loc;
        if (zr < N) *(uint4*)(zh + (size_t)zr * 128 + u16 * 8) = Z;
    };

    // prologue: stage this CTA's first tile into buffer 0
    int tile = blockIdx.x;
    if (tile < ntiles) {
        #pragma unroll
        for (int p = 0; p < 4; p++) {
            float4 A0, A1; ld_pass(p, tile * 64, A0, A1); st_pass(p, tile * 64, A0, A1, 0);
        }
    }
    __syncthreads();

    int cur = 0;
    for (; tile < ntiles; tile += gridDim.x) {
        const int rowBase = tile * 64;
        const int nxt = tile + gridDim.x;
        const bool hasNext = nxt < ntiles;
        const uint32_t zbuf = sZb + cur * 16384;

        float c[2][8][4];
        #pragma unroll
        for (int m = 0; m < 2; m++)
            #pragma unroll
            for (int n = 0; n < 8; n++)
                #pragma unroll
                for (int q = 0; q < 4; q++) c[m][n][q] = 0.f;

        // 4 passes: load next-tile rows -> 2 MMA k-steps -> store next-tile rows
        #pragma unroll
        for (int p = 0; p < 4; p++) {
            float4 A0, A1;
            if (hasNext) ld_pass(p, nxt * 64, A0, A1);
            #pragma unroll
            for (int ks2 = 0; ks2 < 2; ks2++) {
                const int kk = p * 2 + ks2;      // k-step 0..7
                uint32_t a[2][4];
                #pragma unroll
                for (int mt = 0; mt < 2; mt++)
                    ldsm4(a[mt][0], a[mt][1], a[mt][2], a[mt][3],
                          zbuf + (uint32_t)(32 * wy + 16 * mt + rA) * 256
                               + (uint32_t)(((kk * 2 + cA) ^ l7) << 4));
                #pragma unroll
                for (int g = 0; g < 4; g++) {
                    uint32_t b[4];
                    ldsm4(b[0], b[1], b[2], b[3],
                          sWb + (uint32_t)(64 * wx + 16 * g + rBoff) * 256
                              + (uint32_t)(((kk * 2 + cB) ^ l7) << 4));
                    #pragma unroll
                    for (int mt = 0; mt < 2; mt++) {
                        mma_f16(c[mt][2*g  ][0], c[mt][2*g  ][1], c[mt][2*g  ][2], c[mt][2*g  ][3],
                                a[mt][0], a[mt][1], a[mt][2], a[mt][3], b[0], b[1]);
                        mma_f16(c[mt][2*g+1][0], c[mt][2*g+1][1], c[mt][2*g+1][2], c[mt][2*g+1][3],
                                a[mt][0], a[mt][1], a[mt][2], a[mt][3], b[2], b[3]);
                    }
                }
            }
            if (hasNext) st_pass(p, nxt * 64, A0, A1, cur ^ 1);
        }
        __syncthreads();   // next buffer fully staged; cur buffer MMA-reads done

        // epilogue: P-ordered coalesced AB store (registers + global only)
        #pragma unroll
        for (int mt = 0; mt < 2; mt++) {
            int r0 = rowBase + 32 * wy + 16 * mt + gid;
            int r1 = r0 + 8;
            uint4 o0, o1, p0, p1;
            half2* oa = (half2*)&o0; half2* ob = (half2*)&o1;
            half2* pa = (half2*)&p0; half2* pb = (half2*)&p1;
            #pragma unroll
            for (int nt = 0; nt < 4; nt++) {
                oa[nt] = __floats2half2_rn(c[mt][nt][0],     c[mt][nt][1]);
                ob[nt] = __floats2half2_rn(c[mt][nt + 4][0], c[mt][nt + 4][1]);
                pa[nt] = __floats2half2_rn(c[mt][nt][2],     c[mt][nt][3]);
                pb[nt] = __floats2half2_rn(c[mt][nt + 4][2], c[mt][nt + 4][3]);
            }
            if (r0 < N) {
                *(uint4*)(AB + (size_t)r0 * 256 + jb)     = o0;
                *(uint4*)(AB + (size_t)r0 * 256 + jb + 8) = o1;
            }
            if (r1 < N) {
                *(uint4*)(AB + (size_t)r1 * 256 + jb)     = p0;
                *(uint4*)(AB + (size_t)r1 * 256 + jb + 8) = p1;
            }
        }
        cur ^= 1;
    }
}

// ---------------------------------------------------------------------------
// Kernel 2 (unchanged from R13/R14): 64-edge tiles; coalesced gathers;
// cross-tile double buffering; b1 folded into S.
// ---------------------------------------------------------------------------
#define K2_SF   32768
#define K2_SS   65536
#define K2_SP   100352
#define K2_SMEM 101376

struct G4 { uint4 U, V, A, B; };

__global__ __launch_bounds__(256, 2) void edge_mlp(
    const __half* __restrict__ zh, const int* __restrict__ eidx,
    const float* __restrict__ b2, const __half* __restrict__ AB,
    float* __restrict__ out, int E, int ntiles)
{
    extern __shared__ __align__(16) unsigned char smem[];
    float* sP = (float*)(smem + K2_SP);

    const int tid  = threadIdx.x;
    const int warp = tid >> 5;
    const int lane = tid & 31;
    const int wy = warp >> 2, wx = warp & 3;
    const int gid = lane >> 2, tig = lane & 3;
    const int l7 = lane & 7;

    #pragma unroll
    for (int p = 0; p < 8; p++) {
        int i = p * 256 + tid;
        int j = i >> 4, uu = i & 15;
        uint4 w = __ldg((const uint4*)g_Wc + (size_t)j * 16 + uu);
        *(uint4*)(smem + j * 256 + ((uu ^ (j & 7)) << 4)) = w;
    }

    const uint32_t sWb = (uint32_t)__cvta_generic_to_shared(smem);
    const uint32_t sFb = sWb + K2_SF;
    const int rA = lane & 15;
    const int cA = lane >> 4;
    const int rBoff = ((lane >> 4) & 1) * 8 + l7;
    const int cB = (lane >> 3) & 1;

    const int eh  = lane >> 4;
    const int u16 = lane & 15;
    const float bias2 = __ldg(b2);

    const uint4 B1 = *(const uint4*)(g_b1h + u16 * 8);
    float w2r[4][2];
    #pragma unroll
    for (int nt = 0; nt < 4; nt++) {
        int j = 32 * wx + 8 * nt + 2 * tig;
        w2r[nt][0] = __ldg(g_w2p + j); w2r[nt][1] = __ldg(g_w2p + j + 1);
    }
    __syncthreads();

    auto ld_pass = [&](int p, int base, G4& g) {
        int e_loc = p * 16 + warp * 2 + eh;
        int ge = base + e_loc;
        int u = 0, v = 0;
        if (ge < E) { u = eidx[ge]; v = eidx[E + ge]; }
        g.U = __ldg((const uint4*)(zh + (size_t)u * 128) + u16);
        g.V = __ldg((const uint4*)(zh + (size_t)v * 128) + u16);
        g.A = __ldg((const uint4*)(AB + (size_t)u * 256) + u16);
        g.B = __ldg((const uint4*)(AB + (size_t)v * 256 + 128) + u16);
    };
    auto st_pass = [&](int p, const G4& g, int nb) {
        int e_loc = p * 16 + warp * 2 + eh;
        const half2* up = (const half2*)&g.U;
        const half2* vp = (const half2*)&g.V;
        uint4 D; half2* dp = (half2*)&D;
        #pragma unroll
        for (int i = 0; i < 4; i++) dp[i] = __habs2(__hsub2(up[i], vp[i]));
        *(uint4*)(smem + K2_SF + nb * 16384 + e_loc * 256 + ((u16 ^ (e_loc & 7)) << 4)) = D;
        const half2* ap = (const half2*)&g.A;
        const half2* bp = (const half2*)&g.B;
        const half2* b1p = (const half2*)&B1;
        uint4 S; half2* sp = (half2*)&S;
        #pragma unroll
        for (int i = 0; i < 4; i++) sp[i] = __hadd2(__hadd2(ap[i], bp[i]), b1p[i]);
        *(uint4*)(smem + K2_SS + nb * 17408 + e_loc * 272 + u16 * 16) = S;
    };

    int tile = blockIdx.x;
    if (tile < ntiles) {
        #pragma unroll
        for (int p = 0; p < 4; p++) { G4 g; ld_pass(p, tile * 64, g); st_pass(p, g, 0); }
    }
    __syncthreads();

    int cur = 0;
    for (; tile < ntiles; tile += gridDim.x) {
        const int eBase = tile * 64;
        const int nxt = tile + gridDim.x;
        const bool hasNext = nxt < ntiles;
        const uint32_t fbuf = sFb + cur * 16384;
        const __half* sS16 = (const __half*)(smem + K2_SS + cur * 17408);

        float c[2][4][4];
        #pragma unroll
        for (int m = 0; m < 2; m++)
            #pragma unroll
            for (int n = 0; n < 4; n++)
                #pragma unroll
                for (int q = 0; q < 4; q++) c[m][n][q] = 0.f;

        #pragma unroll
        for (int p = 0; p < 4; p++) {
            G4 g;
            if (hasNext) ld_pass(p, nxt * 64, g);
            #pragma unroll
            for (int ks2 = 0; ks2 < 2; ks2++) {
                const int kk = p * 2 + ks2;
                uint32_t a[2][4];
                #pragma unroll
                for (int mt = 0; mt < 2; mt++)
                    ldsm4(a[mt][0], a[mt][1], a[mt][2], a[mt][3],
                          fbuf + (uint32_t)(32 * wy + 16 * mt + rA) * 256
                               + (uint32_t)(((kk * 2 + cA) ^ l7) << 4));
                #pragma unroll
                for (int g2 = 0; g2 < 2; g2++) {
                    uint32_t b[4];
                    ldsm4(b[0], b[1], b[2], b[3],
                          sWb + (uint32_t)(32 * wx + 16 * g2 + rBoff) * 256
                              + (uint32_t)(((kk * 2 + cB) ^ l7) << 4));
                    #pragma unroll
                    for (int mt = 0; mt < 2; mt++) {
                        mma_f16(c[mt][2*g2  ][0], c[mt][2*g2  ][1], c[mt][2*g2  ][2], c[mt][2*g2  ][3],
                                a[mt][0], a[mt][1], a[mt][2], a[mt][3], b[0], b[1]);
                        mma_f16(c[mt][2*g2+1][0], c[mt][2*g2+1][1], c[mt][2*g2+1][2], c[mt][2*g2+1][3],
                                a[mt][0], a[mt][1], a[mt][2], a[mt][3], b[2], b[3]);
                    }
                }
            }
            if (hasNext) st_pass(p, g, cur ^ 1);
        }

        float pe[2][2] = {{0.f, 0.f}, {0.f, 0.f}};
        #pragma unroll
        for (int mt = 0; mt < 2; mt++) {
            int e0 = 32 * wy + 16 * mt + gid;
            #pragma unroll
            for (int nt = 0; nt < 4; nt++) {
                int j = 32 * wx + 8 * nt + 2 * tig;
                float2 s0 = __half22float2(*(const half2*)(sS16 + e0 * 136 + j));
                float2 s1 = __half22float2(*(const half2*)(sS16 + (e0 + 8) * 136 + j));
                pe[mt][0] += fmaxf(c[mt][nt][0] + s0.x, 0.f) * w2r[nt][0]
                           + fmaxf(c[mt][nt][1] + s0.y, 0.f) * w2r[nt][1];
                pe[mt][1] += fmaxf(c[mt][nt][2] + s1.x, 0.f) * w2r[nt][0]
                           + fmaxf(c[mt][nt][3] + s1.y, 0.f) * w2r[nt][1];
            }
        }
        #pragma unroll
        for (int mt = 0; mt < 2; mt++)
            #pragma unroll
            for (int hh = 0; hh < 2; hh++) {
                float p = pe[mt][hh];
                p += __shfl_xor_sync(0xFFFFFFFFu, p, 1);
                p += __shfl_xor_sync(0xFFFFFFFFu, p, 2);
                if (tig == 0) sP[(32 * wy + 16 * mt + 8 * hh + gid) * 4 + wx] = p;
            }
        __syncthreads();

        if (tid < 64) {
            int g = eBase + tid;
            if (g < E)
                out[g] = sP[tid * 4] + sP[tid * 4 + 1] + sP[tid * 4 + 2] + sP[tid * 4 + 3] + bias2;
        }
        __syncthreads();
        cur ^= 1;
    }
}

extern "C" void kernel_launch(void* const* d_in, const int* in_sizes, int n_in,
                              void* d_out, int out_size) {
    const float* z    = (const float*)d_in[0];
    const int*   eidx = (const int*)d_in[1];   // int32 on the wire
    const float* W1   = (const float*)d_in[2];
    const float* b1   = (const float*)d_in[3];
    const float* W2   = (const float*)d_in[4];
    const float* b2   = (const float*)d_in[5];
    float*       out  = (float*)d_out;

    const int N = in_sizes[0] / DIM;           // 100000
    const int E = in_sizes[1] / 2;             // 500000
    const int t1 = (N + 63) / 64;              // 1563
    const int t2 = (E + 63) / 64;              // 7813

    __half* AB = nullptr; __half* ZH = nullptr;
    cudaGetSymbolAddress((void**)&AB, g_AB);
    cudaGetSymbolAddress((void**)&ZH, g_zh);

    const int k1_smem = 65536 + 32768;         // 98304
    cudaFuncSetAttribute(ab_gemm,  cudaFuncAttributeMaxDynamicSharedMemorySize, k1_smem);
    cudaFuncSetAttribute(edge_mlp, cudaFuncAttributeMaxDynamicSharedMemorySize, K2_SMEM);

    prep_w<<<194, 256>>>(W1, b1, W2);
    ab_gemm<<<296, 256, k1_smem>>>(z, AB, ZH, N, t1);
    edge_mlp<<<296, 256, K2_SMEM>>>(ZH, eidx, b2, AB, out, E, t2);
}

// round 16
// speedup vs baseline: 5.9238x; 1.0275x over previous
#include <cuda_runtime.h>
#include <cuda_fp16.h>
#include <cstdint>

// MLPDecoder, split + fp16 mma.sync (m16n8k16, fp32 accum); persistent, 2 CTAs/SM.
// R16: prep_w coalesced reads; k2 dynamic tile scheduling (atomic counter,
//      reset by prep_w) + single sync/tile via double-buffered sP/sNxt.
//  P(j) hidden-dim permutation as in R13. edge_index is int32 on the wire.

#define DIM 128
#define NMAX 100000
#define K2_GRID 296

__device__ __half g_Wab[256 * 128];           // [j][k] fp16 (orig col order)
__device__ __half g_Wc[128 * 128];            // [P(j)][k] fp16
__device__ __half g_b1h[128];                 // P-ordered fp16
__device__ float  g_w2p[128];                 // P-ordered fp32
__device__ __half g_AB[(size_t)NMAX * 256];   // fp16, P-ordered cols
__device__ __half g_zh[(size_t)NMAX * 128];   // fp16 copy of z (written by ab_gemm)
__device__ int    g_ctr;                      // k2 dynamic tile counter

__device__ __forceinline__ int permJ(int j) {
    return (((j >> 6) * 4) + ((j >> 1) & 3)) * 16 + ((j >> 3) & 7) * 2 + (j & 1);
}

__device__ __forceinline__ void ldsm4(uint32_t& r0, uint32_t& r1, uint32_t& r2, uint32_t& r3,
                                      uint32_t addr) {
    asm volatile("ldmatrix.sync.aligned.m8n8.x4.shared.b16 {%0,%1,%2,%3}, [%4];"
                 : "=r"(r0), "=r"(r1), "=r"(r2), "=r"(r3) : "r"(addr));
}
__device__ __forceinline__ void mma_f16(
    float& c0, float& c1, float& c2, float& c3,
    uint32_t a0, uint32_t a1, uint32_t a2, uint32_t a3,
    uint32_t b0, uint32_t b1)
{
    asm volatile(
        "mma.sync.aligned.m16n8k16.row.col.f32.f16.f16.f32 "
        "{%0,%1,%2,%3}, {%4,%5,%6,%7}, {%8,%9}, {%0,%1,%2,%3};"
        : "+f"(c0), "+f"(c1), "+f"(c2), "+f"(c3)
        : "r"(a0), "r"(a1), "r"(a2), "r"(a3), "r"(b0), "r"(b1));
}

// ---------------------------------------------------------------------------
// prep: k-major iteration -> coalesced W1 reads, scattered (async) writes.
__global__ void prep_w(const float* __restrict__ W1, const float* __restrict__ b1,
                       const float* __restrict__ W2) {
    int i = blockIdx.x * 256 + threadIdx.x;
    if (i == 0) g_ctr = K2_GRID;           // reset dynamic scheduler each launch
    if (i < 32768) {                       // Wab: k = i>>8, j = i&255
        int k = i >> 8, j = i & 255;
        g_Wab[j * 128 + k] = __float2half_rn(W1[(k + (j < 128 ? 0 : 128)) * 128 + (j & 127)]);
    } else if (i < 49152) {                // Wc: k = l>>7, j = l&127
        int l = i - 32768;
        int k = l >> 7, j = l & 127;
        g_Wc[permJ(j) * 128 + k] = __float2half_rn(W1[(256 + k) * 128 + j]);
    } else if (i < 49280) {
        int j = i - 49152;
        g_b1h[permJ(j)] = __float2half_rn(b1[j]);
    } else if (i < 49408) {
        int j = i - 49280;
        g_w2p[permJ(j)] = W2[j];
    }
}

// ---------------------------------------------------------------------------
// Kernel 1 (unchanged from R15): AB = z @ [W1a|W1b] + zh = fp16(z).
// 64r x 256c tiles, cross-tile double-buffered z staging, 1 sync/tile.
// ---------------------------------------------------------------------------
__global__ __launch_bounds__(256, 2) void ab_gemm(
    const float* __restrict__ z, __half* __restrict__ AB,
    __half* __restrict__ zh, int N, int ntiles)
{
    extern __shared__ __align__(16) unsigned char smem[];
    const int tid  = threadIdx.x;
    const int warp = tid >> 5;
    const int lane = tid & 31;
    const int wy = warp >> 2, wx = warp & 3;
    const int gid = lane >> 2, tig = lane & 3;
    const int l7 = lane & 7;

    #pragma unroll
    for (int p = 0; p < 16; p++) {
        int i = p * 256 + tid;
        int j = i >> 4, uu = i & 15;
        uint4 w = __ldg((const uint4*)g_Wab + (size_t)j * 16 + uu);
        *(uint4*)(smem + j * 256 + ((uu ^ (j & 7)) << 4)) = w;
    }

    const uint32_t sWb = (uint32_t)__cvta_generic_to_shared(smem);
    const uint32_t sZb = sWb + 65536;
    const int rA = lane & 15;
    const int cA = lane >> 4;
    const int rBoff = ((lane >> 4) & 1) * 8 + l7;
    const int cB = (lane >> 3) & 1;

    const int eh  = lane >> 4;
    const int u16 = lane & 15;
    const int jb  = (wx * 4 + tig) * 16;
    __syncthreads();

    auto ld_pass = [&](int p, int base, float4& A0, float4& A1) {
        int r_loc = p * 16 + warp * 2 + eh;
        int zr = base + r_loc; if (zr >= N) zr = N - 1;
        const float4* src = (const float4*)(z + (size_t)zr * 128) + u16 * 2;
        A0 = __ldg(src); A1 = __ldg(src + 1);
    };
    auto st_pass = [&](int p, int base, float4 A0, float4 A1, int nb) {
        int r_loc = p * 16 + warp * 2 + eh;
        uint4 Z; half2* zp = (half2*)&Z;
        zp[0] = __floats2half2_rn(A0.x, A0.y);
        zp[1] = __floats2half2_rn(A0.z, A0.w);
        zp[2] = __floats2half2_rn(A1.x, A1.y);
        zp[3] = __floats2half2_rn(A1.z, A1.w);
        *(uint4*)(smem + 65536 + nb * 16384 + r_loc * 256 + ((u16 ^ (r_loc & 7)) << 4)) = Z;
        int zr = base + r_loc;
        if (zr < N) *(uint4*)(zh + (size_t)zr * 128 + u16 * 8) = Z;
    };

    int tile = blockIdx.x;
    if (tile < ntiles) {
        #pragma unroll
        for (int p = 0; p < 4; p++) {
            float4 A0, A1; ld_pass(p, tile * 64, A0, A1); st_pass(p, tile * 64, A0, A1, 0);
        }
    }
    __syncthreads();

    int cur = 0;
    for (; tile < ntiles; tile += gridDim.x) {
        const int rowBase = tile * 64;
        const int nxt = tile + gridDim.x;
        const bool hasNext = nxt < ntiles;
        const uint32_t zbuf = sZb + cur * 16384;

        float c[2][8][4];
        #pragma unroll
        for (int m = 0; m < 2; m++)
            #pragma unroll
            for (int n = 0; n < 8; n++)
                #pragma unroll
                for (int q = 0; q < 4; q++) c[m][n][q] = 0.f;

        #pragma unroll
        for (int p = 0; p < 4; p++) {
            float4 A0, A1;
            if (hasNext) ld_pass(p, nxt * 64, A0, A1);
            #pragma unroll
            for (int ks2 = 0; ks2 < 2; ks2++) {
                const int kk = p * 2 + ks2;
                uint32_t a[2][4];
                #pragma unroll
                for (int mt = 0; mt < 2; mt++)
                    ldsm4(a[mt][0], a[mt][1], a[mt][2], a[mt][3],
                          zbuf + (uint32_t)(32 * wy + 16 * mt + rA) * 256
                               + (uint32_t)(((kk * 2 + cA) ^ l7) << 4));
                #pragma unroll
                for (int g = 0; g < 4; g++) {
                    uint32_t b[4];
                    ldsm4(b[0], b[1], b[2], b[3],
                          sWb + (uint32_t)(64 * wx + 16 * g + rBoff) * 256
                              + (uint32_t)(((kk * 2 + cB) ^ l7) << 4));
                    #pragma unroll
                    for (int mt = 0; mt < 2; mt++) {
                        mma_f16(c[mt][2*g  ][0], c[mt][2*g  ][1], c[mt][2*g  ][2], c[mt][2*g  ][3],
                                a[mt][0], a[mt][1], a[mt][2], a[mt][3], b[0], b[1]);
                        mma_f16(c[mt][2*g+1][0], c[mt][2*g+1][1], c[mt][2*g+1][2], c[mt][2*g+1][3],
                                a[mt][0], a[mt][1], a[mt][2], a[mt][3], b[2], b[3]);
                    }
                }
            }
            if (hasNext) st_pass(p, nxt * 64, A0, A1, cur ^ 1);
        }
        __syncthreads();

        #pragma unroll
        for (int mt = 0; mt < 2; mt++) {
            int r0 = rowBase + 32 * wy + 16 * mt + gid;
            int r1 = r0 + 8;
            uint4 o0, o1, p0, p1;
            half2* oa = (half2*)&o0; half2* ob = (half2*)&o1;
            half2* pa = (half2*)&p0; half2* pb = (half2*)&p1;
            #pragma unroll
            for (int nt = 0; nt < 4; nt++) {
                oa[nt] = __floats2half2_rn(c[mt][nt][0],     c[mt][nt][1]);
                ob[nt] = __floats2half2_rn(c[mt][nt + 4][0], c[mt][nt + 4][1]);
                pa[nt] = __floats2half2_rn(c[mt][nt][2],     c[mt][nt][3]);
                pb[nt] = __floats2half2_rn(c[mt][nt + 4][2], c[mt][nt + 4][3]);
            }
            if (r0 < N) {
                *(uint4*)(AB + (size_t)r0 * 256 + jb)     = o0;
                *(uint4*)(AB + (size_t)r0 * 256 + jb + 8) = o1;
            }
            if (r1 < N) {
                *(uint4*)(AB + (size_t)r1 * 256 + jb)     = p0;
                *(uint4*)(AB + (size_t)r1 * 256 + jb + 8) = p1;
            }
        }
        cur ^= 1;
    }
}

// ---------------------------------------------------------------------------
// Kernel 2 (R16): dynamic tile scheduling + 1 sync/tile.
// smem: sW 32768 + sF 2x16384 + sS16 2x17408 + sP 2x1024 + sNxt 16 = 102432.
// ---------------------------------------------------------------------------
#define K2_SF   32768
#define K2_SS   65536
#define K2_SP   100352
#define K2_SNXT 102400
#define K2_SMEM 102432

struct G4 { uint4 U, V, A, B; };

__global__ __launch_bounds__(256, 2) void edge_mlp(
    const __half* __restrict__ zh, const int* __restrict__ eidx,
    const float* __restrict__ b2, const __half* __restrict__ AB,
    float* __restrict__ out, int E, int ntiles)
{
    extern __shared__ __align__(16) unsigned char smem[];
    float* sP   = (float*)(smem + K2_SP);     // [2 bufs][64e][4]
    int*   sNxt = (int*)(smem + K2_SNXT);     // [2 slots]

    const int tid  = threadIdx.x;
    const int warp = tid >> 5;
    const int lane = tid & 31;
    const int wy = warp >> 2, wx = warp & 3;
    const int gid = lane >> 2, tig = lane & 3;
    const int l7 = lane & 7;

    #pragma unroll
    for (int p = 0; p < 8; p++) {
        int i = p * 256 + tid;
        int j = i >> 4, uu = i & 15;
        uint4 w = __ldg((const uint4*)g_Wc + (size_t)j * 16 + uu);
        *(uint4*)(smem + j * 256 + ((uu ^ (j & 7)) << 4)) = w;
    }

    const uint32_t sWb = (uint32_t)__cvta_generic_to_shared(smem);
    const uint32_t sFb = sWb + K2_SF;
    const int rA = lane & 15;
    const int cA = lane >> 4;
    const int rBoff = ((lane >> 4) & 1) * 8 + l7;
    const int cB = (lane >> 3) & 1;

    const int eh  = lane >> 4;
    const int u16 = lane & 15;
    const float bias2 = __ldg(b2);

    const uint4 B1 = *(const uint4*)(g_b1h + u16 * 8);
    float w2r[4][2];
    #pragma unroll
    for (int nt = 0; nt < 4; nt++) {
        int j = 32 * wx + 8 * nt + 2 * tig;
        w2r[nt][0] = __ldg(g_w2p + j); w2r[nt][1] = __ldg(g_w2p + j + 1);
    }

    auto ld_pass = [&](int p, int base, G4& g) {
        int e_loc = p * 16 + warp * 2 + eh;
        int ge = base + e_loc;
        int u = 0, v = 0;
        if (ge < E) { u = eidx[ge]; v = eidx[E + ge]; }
        g.U = __ldg((const uint4*)(zh + (size_t)u * 128) + u16);
        g.V = __ldg((const uint4*)(zh + (size_t)v * 128) + u16);
        g.A = __ldg((const uint4*)(AB + (size_t)u * 256) + u16);
        g.B = __ldg((const uint4*)(AB + (size_t)v * 256 + 128) + u16);
    };
    auto st_pass = [&](int p, const G4& g, int nb) {
        int e_loc = p * 16 + warp * 2 + eh;
        const half2* up = (const half2*)&g.U;
        const half2* vp = (const half2*)&g.V;
        uint4 D; half2* dp = (half2*)&D;
        #pragma unroll
        for (int i = 0; i < 4; i++) dp[i] = __habs2(__hsub2(up[i], vp[i]));
        *(uint4*)(smem + K2_SF + nb * 16384 + e_loc * 256 + ((u16 ^ (e_loc & 7)) << 4)) = D;
        const half2* ap = (const half2*)&g.A;
        const half2* bp = (const half2*)&g.B;
        const half2* b1p = (const half2*)&B1;
        uint4 S; half2* sp = (half2*)&S;
        #pragma unroll
        for (int i = 0; i < 4; i++) sp[i] = __hadd2(__hadd2(ap[i], bp[i]), b1p[i]);
        *(uint4*)(smem + K2_SS + nb * 17408 + e_loc * 272 + u16 * 16) = S;
    };

    // prologue: stage tile blockIdx into buffer 0; fetch first dynamic tile
    int cur = blockIdx.x;
    #pragma unroll
    for (int p = 0; p < 4; p++) { G4 g; ld_pass(p, cur * 64, g); st_pass(p, g, 0); }
    if (tid == 0) sNxt[1] = atomicAdd(&g_ctr, 1);
    __syncthreads();
    int nx1 = sNxt[1];
    int curbuf = 0;

    while (true) {
        const bool hasNext = nx1 < ntiles;
        if (tid == 0 && hasNext) sNxt[curbuf] = atomicAdd(&g_ctr, 1);

        const uint32_t fbuf = sFb + curbuf * 16384;
        const __half* sS16 = (const __half*)(smem + K2_SS + curbuf * 17408);

        float c[2][4][4];
        #pragma unroll
        for (int m = 0; m < 2; m++)
            #pragma unroll
            for (int n = 0; n < 4; n++)
                #pragma unroll
                for (int q = 0; q < 4; q++) c[m][n][q] = 0.f;

        #pragma unroll
        for (int p = 0; p < 4; p++) {
            G4 g;
            if (hasNext) ld_pass(p, nx1 * 64, g);
            #pragma unroll
            for (int ks2 = 0; ks2 < 2; ks2++) {
                const int kk = p * 2 + ks2;
                uint32_t a[2][4];
                #pragma unroll
                for (int mt = 0; mt < 2; mt++)
                    ldsm4(a[mt][0], a[mt][1], a[mt][2], a[mt][3],
                          fbuf + (uint32_t)(32 * wy + 16 * mt + rA) * 256
                               + (uint32_t)(((kk * 2 + cA) ^ l7) << 4));
                #pragma unroll
                for (int g2 = 0; g2 < 2; g2++) {
                    uint32_t b[4];
                    ldsm4(b[0], b[1], b[2], b[3],
                          sWb + (uint32_t)(32 * wx + 16 * g2 + rBoff) * 256
                              + (uint32_t)(((kk * 2 + cB) ^ l7) << 4));
                    #pragma unroll
                    for (int mt = 0; mt < 2; mt++) {
                        mma_f16(c[mt][2*g2  ][0], c[mt][2*g2  ][1], c[mt][2*g2  ][2], c[mt][2*g2  ][3],
                                a[mt][0], a[mt][1], a[mt][2], a[mt][3], b[0], b[1]);
                        mma_f16(c[mt][2*g2+1][0], c[mt][2*g2+1][1], c[mt][2*g2+1][2], c[mt][2*g2+1][3],
                                a[mt][0], a[mt][1], a[mt][2], a[mt][3], b[2], b[3]);
                    }
                }
            }
            if (hasNext) st_pass(p, g, curbuf ^ 1);
        }

        float pe[2][2] = {{0.f, 0.f}, {0.f, 0.f}};
        #pragma unroll
        for (int mt = 0; mt < 2; mt++) {
            int e0 = 32 * wy + 16 * mt + gid;
            #pragma unroll
            for (int nt = 0; nt < 4; nt++) {
                int j = 32 * wx + 8 * nt + 2 * tig;
                float2 s0 = __half22float2(*(const half2*)(sS16 + e0 * 136 + j));
                float2 s1 = __half22float2(*(const half2*)(sS16 + (e0 + 8) * 136 + j));
                pe[mt][0] += fmaxf(c[mt][nt][0] + s0.x, 0.f) * w2r[nt][0]
                           + fmaxf(c[mt][nt][1] + s0.y, 0.f) * w2r[nt][1];
                pe[mt][1] += fmaxf(c[mt][nt][2] + s1.x, 0.f) * w2r[nt][0]
                           + fmaxf(c[mt][nt][3] + s1.y, 0.f) * w2r[nt][1];
            }
        }
        float* sPb = sP + curbuf * 256;
        #pragma unroll
        for (int mt = 0; mt < 2; mt++)
            #pragma unroll
            for (int hh = 0; hh < 2; hh++) {
                float p = pe[mt][hh];
                p += __shfl_xor_sync(0xFFFFFFFFu, p, 1);
                p += __shfl_xor_sync(0xFFFFFFFFu, p, 2);
                if (tig == 0) sPb[(32 * wy + 16 * mt + 8 * hh + gid) * 4 + wx] = p;
            }
        __syncthreads();     // orders: sP write->read, sNxt write->read, F/S handoff

        if (tid < 64) {
            int g = cur * 64 + tid;
            if (g < E)
                out[g] = sPb[tid * 4] + sPb[tid * 4 + 1] + sPb[tid * 4 + 2] + sPb[tid * 4 + 3] + bias2;
        }
        if (!hasNext) break;
        cur = nx1; nx1 = sNxt[curbuf]; curbuf ^= 1;
    }
}

extern "C" void kernel_launch(void* const* d_in, const int* in_sizes, int n_in,
                              void* d_out, int out_size) {
    const float* z    = (const float*)d_in[0];
    const int*   eidx = (const int*)d_in[1];   // int32 on the wire
    const float* W1   = (const float*)d_in[2];
    const float* b1   = (const float*)d_in[3];
    const float* W2   = (const float*)d_in[4];
    const float* b2   = (const float*)d_in[5];
    float*       out  = (float*)d_out;

    const int N = in_sizes[0] / DIM;           // 100000
    const int E = in_sizes[1] / 2;             // 500000
    const int t1 = (N + 63) / 64;              // 1563
    const int t2 = (E + 63) / 64;              // 7813

    __half* AB = nullptr; __half* ZH = nullptr;
    cudaGetSymbolAddress((void**)&AB, g_AB);
    cudaGetSymbolAddress((void**)&ZH, g_zh);

    const int k1_smem = 65536 + 32768;         // 98304
    cudaFuncSetAttribute(ab_gemm,  cudaFuncAttributeMaxDynamicSharedMemorySize, k1_smem);
    cudaFuncSetAttribute(edge_mlp, cudaFuncAttributeMaxDynamicSharedMemorySize, K2_SMEM);

    prep_w<<<194, 256>>>(W1, b1, W2);
    ab_gemm<<<296, 256, k1_smem>>>(z, AB, ZH, N, t1);
    edge_mlp<<<K2_GRID, 256, K2_SMEM>>>(ZH, eidx, b2, AB, out, E, t2);
}